// round 7
// baseline (speedup 1.0000x reference)
#include <cuda_runtime.h>
#include <cuda_fp16.h>
#include <cstdint>
#include <cstddef>

// ---------------- problem constants ----------------
#define BB    128
#define TT    512
#define II    300
#define HH    150
#define G3    450    // 3H
#define D2    300    // 2H
#define KK    6
#define THD   20
#define CLSN  5

#define KP    320    // padded K for fp16 GEMM (300 -> 320)
#define NPAD  960    // padded N (900 -> 960)

// ---------------- device scratch (static, allocation-free) ----------------
__device__ float g_gi[(size_t)2 * BB * TT * G3];    // [dir][b][t][g]
__device__ float g_seq[(size_t)BB * TT * D2];       // [b][t][d]
__device__ float g_hidden[BB * D2];
__device__ float g_ctxA[KK * D2];
__device__ float g_context[BB * KK * D2];
__device__ float g_energy[(size_t)BB * TT * KK];    // energy, then probs in-place
__device__ float g_pooled[BB * KK * D2];
__device__ float g_regb[BB];
__device__ __half g_xh[(size_t)BB * TT * KP];       // fp16 x, K padded
__device__ __half g_wh[(size_t)NPAD * KP];          // fp16 [Wf;Wb], K padded

// ==========================================================================
// K0a/K0b: fp32 -> fp16 conversion (zero-padded K)
// ==========================================================================
__global__ void __launch_bounds__(256) cvt_x(const float* __restrict__ x)
{
    size_t i = (size_t)blockIdx.x * 256 + threadIdx.x;
    if (i >= (size_t)BB * TT * KP) return;
    int col = (int)(i % KP);
    size_t row = i / KP;
    g_xh[i] = (col < II) ? __float2half_rn(x[row * II + col]) : __float2half(0.f);
}

__global__ void __launch_bounds__(256) cvt_w(const float* __restrict__ Wf,
                                             const float* __restrict__ Wb)
{
    int i = blockIdx.x * 256 + threadIdx.x;
    if (i >= NPAD * KP) return;
    int col = i % KP;
    int row = i / KP;
    float v = 0.f;
    if (col < II && row < 900)
        v = (row < 450) ? Wf[row * II + col] : Wb[(row - 450) * II + col];
    g_wh[i] = __float2half_rn(v);
}

// ==========================================================================
// K1: gi GEMM on tensor cores (mma.sync m16n8k16, fp16 in / fp32 accum)
// ==========================================================================
__device__ __forceinline__ uint32_t s2u(const void* p) {
    return (uint32_t)__cvta_generic_to_shared(p);
}

#define LDSM4(R, addr) \
    asm volatile("ldmatrix.sync.aligned.m8n8.x4.shared.b16 {%0,%1,%2,%3}, [%4];" \
        : "=r"((R)[0]), "=r"((R)[1]), "=r"((R)[2]), "=r"((R)[3]) : "r"(addr))

#define MMA16816(C, A, b0, b1) \
    asm volatile("mma.sync.aligned.m16n8k16.row.col.f32.f16.f16.f32 " \
        "{%0,%1,%2,%3},{%4,%5,%6,%7},{%8,%9},{%0,%1,%2,%3};" \
        : "+f"((C)[0]), "+f"((C)[1]), "+f"((C)[2]), "+f"((C)[3]) \
        : "r"((A)[0]), "r"((A)[1]), "r"((A)[2]), "r"((A)[3]), "r"(b0), "r"(b1))

#define GBM 128
#define GBN 64
#define GBK 32
#define SPAD 40      // smem row stride in halves (80B: conflict-free ldmatrix)

__global__ void __launch_bounds__(256) gi_gemm_mma(
    const float* __restrict__ bf, const float* __restrict__ bb)
{
    __shared__ __half As[2][GBM][SPAD];
    __shared__ __half Bs[2][GBN][SPAD];

    const int tid  = threadIdx.x;
    const int m0   = blockIdx.x * GBM;
    const int n0   = blockIdx.y * GBN;
    const int warp = tid >> 5;
    const int lane = tid & 31;
    const int wm   = (warp >> 1) * 32;   // 0,32,64,96
    const int wn   = (warp & 1) * 32;    // 0,32

    const int gr = tid >> 2;            // 0..63
    const int gc = (tid & 3) * 8;       // half offset
    const __half* aP0 = g_xh + (size_t)(m0 + gr) * KP + gc;
    const __half* aP1 = g_xh + (size_t)(m0 + gr + 64) * KP + gc;
    const __half* bP  = g_wh + (size_t)(n0 + gr) * KP + gc;

    const uint32_t aAddr = s2u(&As[0][wm + (lane & 15)][(lane >> 4) * 8]);
    const uint32_t bAddr = s2u(&Bs[0][wn + ((lane >> 4) << 3) + (lane & 7)][((lane >> 3) & 1) * 8]);
    const uint32_t ABUF = GBM * SPAD * 2;   // 10240
    const uint32_t BBUF = GBN * SPAD * 2;   // 5120
    const uint32_t RSTR = SPAD * 2;         // 80 bytes / row

    float acc[2][4][4];
    #pragma unroll
    for (int i = 0; i < 2; i++)
        #pragma unroll
        for (int j = 0; j < 4; j++)
            #pragma unroll
            for (int q = 0; q < 4; q++) acc[i][j][q] = 0.f;

    uint4 ra0 = *(const uint4*)aP0;
    uint4 ra1 = *(const uint4*)aP1;
    uint4 rb  = *(const uint4*)bP;
    *(uint4*)&As[0][gr][gc]      = ra0;
    *(uint4*)&As[0][gr + 64][gc] = ra1;
    *(uint4*)&Bs[0][gr][gc]      = rb;
    __syncthreads();

    const int NKT = KP / GBK;   // 10
    for (int kt = 0; kt < NKT; kt++) {
        const int buf = kt & 1;
        if (kt < NKT - 1) {
            const size_t off = (size_t)(kt + 1) * GBK;
            ra0 = *(const uint4*)(aP0 + off);
            ra1 = *(const uint4*)(aP1 + off);
            rb  = *(const uint4*)(bP + off);
        }
        #pragma unroll
        for (int ks = 0; ks < 2; ks++) {
            uint32_t A0[4], A1[4], B0[4], B1[4];
            const uint32_t ao = aAddr + buf * ABUF + ks * 32;
            const uint32_t bo = bAddr + buf * BBUF + ks * 32;
            LDSM4(A0, ao);
            LDSM4(A1, ao + 16 * RSTR);
            LDSM4(B0, bo);
            LDSM4(B1, bo + 16 * RSTR);
            MMA16816(acc[0][0], A0, B0[0], B0[1]);
            MMA16816(acc[0][1], A0, B0[2], B0[3]);
            MMA16816(acc[0][2], A0, B1[0], B1[1]);
            MMA16816(acc[0][3], A0, B1[2], B1[3]);
            MMA16816(acc[1][0], A1, B0[0], B0[1]);
            MMA16816(acc[1][1], A1, B0[2], B0[3]);
            MMA16816(acc[1][2], A1, B1[0], B1[1]);
            MMA16816(acc[1][3], A1, B1[2], B1[3]);
        }
        if (kt < NKT - 1) {
            const int nb = buf ^ 1;
            *(uint4*)&As[nb][gr][gc]      = ra0;
            *(uint4*)&As[nb][gr + 64][gc] = ra1;
            *(uint4*)&Bs[nb][gr][gc]      = rb;
        }
        __syncthreads();
    }

    // epilogue: scatter to g_gi with bias
    const int cr = lane >> 2;           // row within 8
    const int cc = (lane & 3) * 2;      // col pair
    #pragma unroll
    for (int mi = 0; mi < 2; mi++) {
        #pragma unroll
        for (int ni = 0; ni < 4; ni++) {
            const int n = n0 + wn + ni * 8 + cc;
            if (n + 1 < 900) {
                const int dir = (n >= 450);
                const int g   = n - dir * 450;
                const float b0v = dir ? bb[g]     : bf[g];
                const float b1v = dir ? bb[g + 1] : bf[g + 1];
                const size_t dbase = (size_t)dir * BB * TT * G3;
                const int m = m0 + wm + mi * 16 + cr;
                float* p0 = g_gi + dbase + (size_t)m * G3 + g;
                float* p1 = g_gi + dbase + (size_t)(m + 8) * G3 + g;
                p0[0] = acc[mi][ni][0] + b0v;
                p0[1] = acc[mi][ni][1] + b1v;
                p1[0] = acc[mi][ni][2] + b0v;
                p1[1] = acc[mi][ni][3] + b1v;
            }
        }
    }
}

// ==========================================================================
// K2: GRU scan — register-resident weights + BATCH-PIPELINED phases.
//     Phase X(s): prefetch gi_A(s) | matvec A(s) | gate B(s-1) | bar
//     Phase Y(s): prefetch gi_B(s) | matvec B(s) | gate A(s)   | bar
//     Gating (MUFU) overlaps the other batch's matvec (fma pipe).
// ==========================================================================
__device__ __forceinline__ float matvec_row(const __half2* __restrict__ w,
                                            const __half* __restrict__ hvec)
{
    const uint4* hp = (const uint4*)hvec;
    float acc = 0.f;
    // 9 chunk-pairs (8-FMA half chains) + 1 final chunk (4-FMA chain)
    #pragma unroll
    for (int cp = 0; cp < 9; cp++) {
        uint4 h0 = hp[2 * cp];
        uint4 h1 = hp[2 * cp + 1];
        const __half2* a = (const __half2*)&h0;
        const __half2* b = (const __half2*)&h1;
        __half2 s0 = __floats2half2_rn(0.f, 0.f);
        #pragma unroll
        for (int q = 0; q < 4; q++) s0 = __hfma2(w[cp * 8 + q], a[q], s0);
        #pragma unroll
        for (int q = 0; q < 4; q++) s0 = __hfma2(w[cp * 8 + 4 + q], b[q], s0);
        float2 f = __half22float2(s0);
        acc += f.x + f.y;
    }
    {
        uint4 h0 = hp[18];
        const __half2* a = (const __half2*)&h0;
        __half2 s0 = __floats2half2_rn(0.f, 0.f);
        #pragma unroll
        for (int q = 0; q < 4; q++) s0 = __hfma2(w[72 + q], a[q], s0);
        float2 f = __half22float2(s0);
        acc += f.x + f.y;
    }
    return acc;
}

__device__ __forceinline__ void gru_gate(int j, const float* __restrict__ gh,
                                         float gr, float gz, float gn,
                                         float* __restrict__ hslot,
                                         __half* __restrict__ hhrow,
                                         float* __restrict__ sqp)
{
    float r = 1.f / (1.f + __expf(-(gr + gh[j])));
    float z = 1.f / (1.f + __expf(-(gz + gh[HH + j])));
    float u = gn + r * gh[2 * HH + j];
    float e = __expf(-2.f * u);
    float n = __fdividef(2.f, 1.f + e) - 1.f;   // tanh(u), overflow-safe
    float h = *hslot;
    float hn = (1.f - z) * n + z * h;
    *hslot = hn;
    hhrow[j] = __float2half_rn(hn);
    *sqp = hn;
}

__global__ void __launch_bounds__(480, 1) gru_scan(
    const float* __restrict__ Whh_f, const float* __restrict__ Whh_b,
    const float* __restrict__ bhh_f, const float* __restrict__ bhh_b)
{
    __shared__ __align__(16) __half hh[2][152];   // fp16 h per batch (pad 2)
    __shared__ float hf[304];                     // fp32 master h: [A 0..149][B 150..299]
    __shared__ float ghm[2][452];                 // gh exchange per batch

    const int tid = threadIdx.x;
    const int dir = blockIdx.x >> 6;
    const int b0  = (blockIdx.x & 63) * 2;

    // ---- one-time: this thread's Whh row -> 76 half2 registers ----
    __half2 w[76];
    float bhv = 0.f;
    if (tid < G3) {
        const float* Whh = (dir ? Whh_b : Whh_f) + tid * HH;
        #pragma unroll
        for (int q = 0; q < 75; q++)
            w[q] = __floats2half2_rn(Whh[2 * q], Whh[2 * q + 1]);
        w[75] = __floats2half2_rn(0.f, 0.f);
        bhv = (dir ? bhh_b : bhh_f)[tid];
    }
    for (int i = tid; i < 2 * 152; i += 480) hh[0][i] = __float2half(0.f);
    if (tid < 300) hf[tid] = 0.f;
    __syncthreads();

    const long dstep = dir ? -(long)G3 : (long)G3;
    const long sstep = dir ? -(long)D2 : (long)D2;
    const int  t0    = dir ? (TT - 1) : 0;

    const float* gipA = nullptr; const float* gipB = nullptr;
    float* sqpA = nullptr; float* sqpB = nullptr;
    if (tid < 150) {
        gipA = g_gi + (((size_t)(dir * BB + b0    )) * TT + t0) * G3 + tid;
        gipB = g_gi + (((size_t)(dir * BB + b0 + 1)) * TT + t0) * G3 + tid;
        sqpA = g_seq + (((size_t)(b0    )) * TT + t0) * D2 + dir * HH + tid;
        sqpB = g_seq + (((size_t)(b0 + 1)) * TT + t0) * D2 + dir * HH + tid;
    }

    float pAr = 0.f, pAz = 0.f, pAn = 0.f;   // gi prefetch for gate A
    float pBr = 0.f, pBz = 0.f, pBn = 0.f;   // gi prefetch for gate B

    for (int s = 0; s < TT; s++) {
        // ======== phase X(s): prefetch gi_A(s) | matvec A(s) | gate B(s-1) ========
        if (tid < 150) {
            pAr = gipA[0]; pAz = gipA[HH]; pAn = gipA[2 * HH];
            gipA += dstep;
        }
        if (tid < G3)
            ghm[0][tid] = matvec_row(w, hh[0]) + bhv;
        if (s > 0 && tid < 150) {
            gru_gate(tid, ghm[1], pBr, pBz, pBn, &hf[150 + tid], hh[1], sqpB);
            sqpB += sstep;
        }
        __syncthreads();

        // ======== phase Y(s): prefetch gi_B(s) | matvec B(s) | gate A(s) ========
        if (tid < 150) {
            pBr = gipB[0]; pBz = gipB[HH]; pBn = gipB[2 * HH];
            gipB += dstep;
        }
        if (tid < G3)
            ghm[1][tid] = matvec_row(w, hh[1]) + bhv;
        if (tid < 150) {
            gru_gate(tid, ghm[0], pAr, pAz, pAn, &hf[tid], hh[0], sqpA);
            sqpA += sstep;
        }
        __syncthreads();
    }
    // epilogue: gate B(TT-1)
    if (tid < 150)
        gru_gate(tid, ghm[1], pBr, pBz, pBn, &hf[150 + tid], hh[1], sqpB);
    __syncthreads();

    if (tid < 300) {
        const int nb = tid / 150;
        const int j  = tid - nb * 150;
        g_hidden[(b0 + nb) * D2 + dir * HH + j] = hf[tid];
    }
}

// ==========================================================================
// K3a0: ctxA[k][d] = battn[k][d] + attn_context[k,:] . Wattn[k][:300][d]
// ==========================================================================
__global__ void __launch_bounds__(320) ctxA_kernel(
    const float* __restrict__ attn_context, const float* __restrict__ Wattn,
    const float* __restrict__ battn)
{
    const int k = blockIdx.x;
    const int d = threadIdx.x;
    __shared__ float ac[D2];
    if (d < D2) ac[d] = attn_context[k * D2 + d];
    __syncthreads();
    if (d < D2) {
        float acc = battn[k * D2 + d];
        const float* wp = Wattn + (size_t)k * 600 * D2 + d;
        #pragma unroll 1
        for (int c = 0; c < D2; c += 4) {
            float w0 = wp[(size_t)(c + 0) * D2];
            float w1 = wp[(size_t)(c + 1) * D2];
            float w2 = wp[(size_t)(c + 2) * D2];
            float w3 = wp[(size_t)(c + 3) * D2];
            acc += ac[c] * w0 + ac[c + 1] * w1 + ac[c + 2] * w2 + ac[c + 3] * w3;
        }
        g_ctxA[k * D2 + d] = acc;
    }
}

// ==========================================================================
// K3a: context[b][k][d] = tanh(ctxA[k][d] + hidden[b,:] . Wattn[k][300:][d])
// ==========================================================================
__global__ void __launch_bounds__(320) context_kernel(const float* __restrict__ Wattn)
{
    const int k  = blockIdx.x;
    const int b0 = blockIdx.y * 4;
    const int d  = threadIdx.x;
    __shared__ float hid[4 * D2];
    for (int i = threadIdx.x; i < 4 * D2; i += blockDim.x) hid[i] = g_hidden[b0 * D2 + i];
    __syncthreads();
    if (d < D2) {
        float acc[4];
        const float base = g_ctxA[k * D2 + d];
        #pragma unroll
        for (int bb = 0; bb < 4; bb++) acc[bb] = base;
        const float* wp = Wattn + ((size_t)k * 600 + D2) * D2 + d;
        #pragma unroll 1
        for (int jj = 0; jj < D2; jj += 4) {
            float w0 = wp[(size_t)(jj + 0) * D2];
            float w1 = wp[(size_t)(jj + 1) * D2];
            float w2 = wp[(size_t)(jj + 2) * D2];
            float w3 = wp[(size_t)(jj + 3) * D2];
            #pragma unroll
            for (int bb = 0; bb < 4; bb++) {
                acc[bb] += hid[bb * D2 + jj] * w0 + hid[bb * D2 + jj + 1] * w1
                         + hid[bb * D2 + jj + 2] * w2 + hid[bb * D2 + jj + 3] * w3;
            }
        }
        #pragma unroll
        for (int bb = 0; bb < 4; bb++)
            g_context[((size_t)(b0 + bb) * KK + k) * D2 + d] = tanhf(acc[bb]);
    }
}

// ==========================================================================
// K3b: energy[b][t][k] = seq[b,t,:] . context[b,k,:]
// ==========================================================================
__global__ void __launch_bounds__(256) energy_kernel()
{
    const int b = blockIdx.x;
    __shared__ float ctx[KK * 301];
    __shared__ float seq_s[32 * D2];
    const int tid = threadIdx.x;
    for (int i = tid; i < KK * D2; i += 256) {
        int k = i / D2, d = i % D2;
        ctx[k * 301 + d] = g_context[((size_t)b * KK + k) * D2 + d];
    }
    const int tt = tid >> 3, kk = tid & 7;
    for (int t0 = 0; t0 < TT; t0 += 32) {
        __syncthreads();
        for (int i = tid; i < 32 * D2; i += 256)
            seq_s[i] = g_seq[((size_t)b * TT + t0) * D2 + i];
        __syncthreads();
        if (kk < KK) {
            const float* sr = seq_s + tt * D2;
            const float* cr = ctx + kk * 301;
            float e = 0.f;
            #pragma unroll 4
            for (int d = 0; d < D2; d++) e += sr[d] * cr[d];
            g_energy[((size_t)b * TT + t0 + tt) * KK + kk] = e;
        }
    }
}

// ==========================================================================
// K3c: softmax over T per (b,k), in place on g_energy
// ==========================================================================
__global__ void __launch_bounds__(192) softmax_t()
{
    const int b = blockIdx.x;
    const int k = threadIdx.x >> 5;
    const int lane = threadIdx.x & 31;
    float v[16];
    float m = -1e30f;
    #pragma unroll
    for (int i = 0; i < 16; i++) {
        v[i] = g_energy[((size_t)b * TT + lane + i * 32) * KK + k];
        m = fmaxf(m, v[i]);
    }
    #pragma unroll
    for (int o = 16; o; o >>= 1) m = fmaxf(m, __shfl_xor_sync(0xffffffffu, m, o));
    float ssum = 0.f;
    #pragma unroll
    for (int i = 0; i < 16; i++) { v[i] = __expf(v[i] - m); ssum += v[i]; }
    #pragma unroll
    for (int o = 16; o; o >>= 1) ssum += __shfl_xor_sync(0xffffffffu, ssum, o);
    const float inv = 1.f / ssum;
    #pragma unroll
    for (int i = 0; i < 16; i++)
        g_energy[((size_t)b * TT + lane + i * 32) * KK + k] = v[i] * inv;
}

// ==========================================================================
// K3d: pooled[b][k][d] = sum_t seq[b,t,d] * probs[b,t,k]
// ==========================================================================
__global__ void __launch_bounds__(320) pooled_kernel()
{
    const int b = blockIdx.x;
    const int tid = threadIdx.x;
    __shared__ float seq_s[32 * D2];
    __shared__ float pr[32 * 8];
    float acc[KK];
    #pragma unroll
    for (int k = 0; k < KK; k++) acc[k] = 0.f;
    for (int t0 = 0; t0 < TT; t0 += 32) {
        __syncthreads();
        for (int i = tid; i < 32 * D2; i += 320)
            seq_s[i] = g_seq[((size_t)b * TT + t0) * D2 + i];
        for (int i = tid; i < 32 * KK; i += 320) {
            int tt = i / KK, k = i % KK;
            pr[tt * 8 + k] = g_energy[((size_t)b * TT + t0 + tt) * KK + k];
        }
        __syncthreads();
        if (tid < D2) {
            #pragma unroll 4
            for (int tt = 0; tt < 32; tt++) {
                const float sv = seq_s[tt * D2 + tid];
                #pragma unroll
                for (int k = 0; k < KK; k++) acc[k] += sv * pr[tt * 8 + k];
            }
        }
    }
    if (tid < D2) {
        #pragma unroll
        for (int k = 0; k < KK; k++)
            g_pooled[((size_t)b * KK + k) * D2 + tid] = acc[k];
    }
}

// ==========================================================================
// K3e: topic heads + logits + softmax + per-batch reg term
// ==========================================================================
__global__ void __launch_bounds__(128) head_kernel(
    const float* __restrict__ Wtop, const float* __restrict__ btop,
    const float* __restrict__ Wout, const float* __restrict__ bout,
    float* __restrict__ out)
{
    const int b = blockIdx.x;
    const int tid = threadIdx.x;
    __shared__ float pl[KK * D2];
    __shared__ float cx[KK * D2];
    __shared__ float tp[KK * THD];
    __shared__ float lg[CLSN];
    __shared__ float inorm[KK];
    __shared__ float gsq[KK * KK];
    for (int i = tid; i < KK * D2; i += 128) {
        pl[i] = g_pooled[(size_t)b * KK * D2 + i];
        cx[i] = g_context[(size_t)b * KK * D2 + i];
    }
    __syncthreads();
    if (tid < KK * THD) {
        const int k = tid / THD, h = tid % THD;
        float a = btop[tid];
        const float* pk = pl + k * D2;
        for (int d = 0; d < D2; d++)
            a += pk[d] * Wtop[((size_t)k * D2 + d) * THD + h];
        tp[tid] = fmaxf(a, 0.f);
    }
    if (tid >= 120 && tid < 120 + KK) {
        const int k = tid - 120;
        const float* ck = cx + k * D2;
        float s = 0.f;
        for (int d = 0; d < D2; d++) s += ck[d] * ck[d];
        inorm[k] = 1.f / fmaxf(sqrtf(s), 1e-12f);
    }
    __syncthreads();
    if (tid < CLSN) {
        float L = bout[tid];
        for (int i = 0; i < KK * THD; i++) L += tp[i] * Wout[i * CLSN + tid];
        lg[tid] = L;
    }
    if (tid >= 32 && tid < 32 + KK * KK) {
        const int q = tid - 32;
        const int k = q / KK, j = q % KK;
        const float* ck = cx + k * D2;
        const float* cj = cx + j * D2;
        float gdot = 0.f;
        for (int d = 0; d < D2; d++) gdot += ck[d] * cj[d];
        gdot *= inorm[k] * inorm[j];
        const float diff = gdot - (k == j ? 1.f : 0.f);
        gsq[q] = diff * diff;
    }
    __syncthreads();
    if (tid < CLSN) {
        float m = lg[0];
        #pragma unroll
        for (int i = 1; i < CLSN; i++) m = fmaxf(m, lg[i]);
        float ss = 0.f;
        #pragma unroll
        for (int i = 0; i < CLSN; i++) ss += __expf(lg[i] - m);
        out[b * CLSN + tid] = __expf(lg[tid] - m) / ss;
    }
    if (tid == 0) {
        float ssum = 0.f;
        #pragma unroll
        for (int i = 0; i < KK * KK; i++) ssum += gsq[i];
        g_regb[b] = sqrtf(ssum);
    }
}

// ==========================================================================
// K3f: reg = mean_b(g_regb)
// ==========================================================================
__global__ void __launch_bounds__(128) reg_reduce(float* __restrict__ out, int out_size)
{
    __shared__ float sh[128];
    const int tid = threadIdx.x;
    sh[tid] = g_regb[tid];
    __syncthreads();
    for (int o = 64; o; o >>= 1) {
        if (tid < o) sh[tid] += sh[tid + o];
        __syncthreads();
    }
    if (tid == 0) out[out_size - 1] = sh[0] * (1.f / 128.f);
}

// ==========================================================================
extern "C" void kernel_launch(void* const* d_in, const int* in_sizes, int n_in,
                              void* d_out, int out_size)
{
    const float* x            = (const float*)d_in[0];
    const float* Wih_f        = (const float*)d_in[1];
    const float* Whh_f        = (const float*)d_in[2];
    const float* bih_f        = (const float*)d_in[3];
    const float* bhh_f        = (const float*)d_in[4];
    const float* Wih_b        = (const float*)d_in[5];
    const float* Whh_b        = (const float*)d_in[6];
    const float* bih_b        = (const float*)d_in[7];
    const float* bhh_b        = (const float*)d_in[8];
    const float* attn_context = (const float*)d_in[9];
    const float* Wattn        = (const float*)d_in[10];
    const float* battn        = (const float*)d_in[11];
    const float* Wtop         = (const float*)d_in[12];
    const float* btop         = (const float*)d_in[13];
    const float* Wout         = (const float*)d_in[14];
    const float* bout         = (const float*)d_in[15];
    float* out = (float*)d_out;

    const size_t xtot = (size_t)BB * TT * KP;
    cvt_x<<<(unsigned)((xtot + 255) / 256), 256>>>(x);
    cvt_w<<<(NPAD * KP + 255) / 256, 256>>>(Wih_f, Wih_b);
    gi_gemm_mma<<<dim3((BB * TT) / GBM, NPAD / GBN), 256>>>(bih_f, bih_b);
    gru_scan<<<128, 480>>>(Whh_f, Whh_b, bhh_f, bhh_b);
    ctxA_kernel<<<KK, 320>>>(attn_context, Wattn, battn);
    context_kernel<<<dim3(KK, 32), 320>>>(Wattn);
    energy_kernel<<<BB, 256>>>();
    softmax_t<<<BB, 192>>>();
    pooled_kernel<<<BB, 320>>>();
    head_kernel<<<BB, 128>>>(Wtop, btop, Wout, bout, out);
    reg_reduce<<<1, 128>>>(out, out_size);
}

// round 11
// speedup vs baseline: 1.1748x; 1.1748x over previous
#include <cuda_runtime.h>
#include <cuda_fp16.h>
#include <cstdint>
#include <cstddef>

// ---------------- problem constants ----------------
#define BB    128
#define TT    512
#define II    300
#define HH    150
#define G3    450    // 3H
#define D2    300    // 2H
#define KK    6
#define THD   20
#define CLSN  5

#define KP    320    // padded K for fp16 GEMM (300 -> 320)
#define NPAD  960    // padded N (900 -> 960)

// ---------------- device scratch (static, allocation-free) ----------------
__device__ float g_gi[(size_t)2 * BB * TT * G3];    // [dir][b][t][g]
__device__ float g_seq[(size_t)BB * TT * D2];       // [b][t][d]
__device__ float g_hidden[BB * D2];
__device__ float g_ctxA[KK * D2];
__device__ float g_context[BB * KK * D2];
__device__ float g_energy[(size_t)BB * TT * KK];    // energy, then probs in-place
__device__ float g_pooled[BB * KK * D2];
__device__ float g_regb[BB];
__device__ __half g_xh[(size_t)BB * TT * KP];       // fp16 x, K padded
__device__ __half g_wh[(size_t)NPAD * KP];          // fp16 [Wf;Wb], K padded

// ==========================================================================
// K0a/K0b: fp32 -> fp16 conversion (zero-padded K)
// ==========================================================================
__global__ void __launch_bounds__(256) cvt_x(const float* __restrict__ x)
{
    size_t i = (size_t)blockIdx.x * 256 + threadIdx.x;
    if (i >= (size_t)BB * TT * KP) return;
    int col = (int)(i % KP);
    size_t row = i / KP;
    g_xh[i] = (col < II) ? __float2half_rn(x[row * II + col]) : __float2half(0.f);
}

__global__ void __launch_bounds__(256) cvt_w(const float* __restrict__ Wf,
                                             const float* __restrict__ Wb)
{
    int i = blockIdx.x * 256 + threadIdx.x;
    if (i >= NPAD * KP) return;
    int col = i % KP;
    int row = i / KP;
    float v = 0.f;
    if (col < II && row < 900)
        v = (row < 450) ? Wf[row * II + col] : Wb[(row - 450) * II + col];
    g_wh[i] = __float2half_rn(v);
}

// ==========================================================================
// K1: gi GEMM on tensor cores (mma.sync m16n8k16, fp16 in / fp32 accum)
// ==========================================================================
__device__ __forceinline__ uint32_t s2u(const void* p) {
    return (uint32_t)__cvta_generic_to_shared(p);
}

#define LDSM4(R, addr) \
    asm volatile("ldmatrix.sync.aligned.m8n8.x4.shared.b16 {%0,%1,%2,%3}, [%4];" \
        : "=r"((R)[0]), "=r"((R)[1]), "=r"((R)[2]), "=r"((R)[3]) : "r"(addr))

#define MMA16816(C, A, b0, b1) \
    asm volatile("mma.sync.aligned.m16n8k16.row.col.f32.f16.f16.f32 " \
        "{%0,%1,%2,%3},{%4,%5,%6,%7},{%8,%9},{%0,%1,%2,%3};" \
        : "+f"((C)[0]), "+f"((C)[1]), "+f"((C)[2]), "+f"((C)[3]) \
        : "r"((A)[0]), "r"((A)[1]), "r"((A)[2]), "r"((A)[3]), "r"(b0), "r"(b1))

#define GBM 128
#define GBN 64
#define GBK 32
#define SPAD 40      // smem row stride in halves (80B: conflict-free ldmatrix)

__global__ void __launch_bounds__(256) gi_gemm_mma(
    const float* __restrict__ bf, const float* __restrict__ bb)
{
    __shared__ __half As[2][GBM][SPAD];
    __shared__ __half Bs[2][GBN][SPAD];

    const int tid  = threadIdx.x;
    const int m0   = blockIdx.x * GBM;
    const int n0   = blockIdx.y * GBN;
    const int warp = tid >> 5;
    const int lane = tid & 31;
    const int wm   = (warp >> 1) * 32;   // 0,32,64,96
    const int wn   = (warp & 1) * 32;    // 0,32

    const int gr = tid >> 2;            // 0..63
    const int gc = (tid & 3) * 8;       // half offset
    const __half* aP0 = g_xh + (size_t)(m0 + gr) * KP + gc;
    const __half* aP1 = g_xh + (size_t)(m0 + gr + 64) * KP + gc;
    const __half* bP  = g_wh + (size_t)(n0 + gr) * KP + gc;

    const uint32_t aAddr = s2u(&As[0][wm + (lane & 15)][(lane >> 4) * 8]);
    const uint32_t bAddr = s2u(&Bs[0][wn + ((lane >> 4) << 3) + (lane & 7)][((lane >> 3) & 1) * 8]);
    const uint32_t ABUF = GBM * SPAD * 2;   // 10240
    const uint32_t BBUF = GBN * SPAD * 2;   // 5120
    const uint32_t RSTR = SPAD * 2;         // 80 bytes / row

    float acc[2][4][4];
    #pragma unroll
    for (int i = 0; i < 2; i++)
        #pragma unroll
        for (int j = 0; j < 4; j++)
            #pragma unroll
            for (int q = 0; q < 4; q++) acc[i][j][q] = 0.f;

    uint4 ra0 = *(const uint4*)aP0;
    uint4 ra1 = *(const uint4*)aP1;
    uint4 rb  = *(const uint4*)bP;
    *(uint4*)&As[0][gr][gc]      = ra0;
    *(uint4*)&As[0][gr + 64][gc] = ra1;
    *(uint4*)&Bs[0][gr][gc]      = rb;
    __syncthreads();

    const int NKT = KP / GBK;   // 10
    for (int kt = 0; kt < NKT; kt++) {
        const int buf = kt & 1;
        if (kt < NKT - 1) {
            const size_t off = (size_t)(kt + 1) * GBK;
            ra0 = *(const uint4*)(aP0 + off);
            ra1 = *(const uint4*)(aP1 + off);
            rb  = *(const uint4*)(bP + off);
        }
        #pragma unroll
        for (int ks = 0; ks < 2; ks++) {
            uint32_t A0[4], A1[4], B0[4], B1[4];
            const uint32_t ao = aAddr + buf * ABUF + ks * 32;
            const uint32_t bo = bAddr + buf * BBUF + ks * 32;
            LDSM4(A0, ao);
            LDSM4(A1, ao + 16 * RSTR);
            LDSM4(B0, bo);
            LDSM4(B1, bo + 16 * RSTR);
            MMA16816(acc[0][0], A0, B0[0], B0[1]);
            MMA16816(acc[0][1], A0, B0[2], B0[3]);
            MMA16816(acc[0][2], A0, B1[0], B1[1]);
            MMA16816(acc[0][3], A0, B1[2], B1[3]);
            MMA16816(acc[1][0], A1, B0[0], B0[1]);
            MMA16816(acc[1][1], A1, B0[2], B0[3]);
            MMA16816(acc[1][2], A1, B1[0], B1[1]);
            MMA16816(acc[1][3], A1, B1[2], B1[3]);
        }
        if (kt < NKT - 1) {
            const int nb = buf ^ 1;
            *(uint4*)&As[nb][gr][gc]      = ra0;
            *(uint4*)&As[nb][gr + 64][gc] = ra1;
            *(uint4*)&Bs[nb][gr][gc]      = rb;
        }
        __syncthreads();
    }

    // epilogue: scatter to g_gi with bias
    const int cr = lane >> 2;           // row within 8
    const int cc = (lane & 3) * 2;      // col pair
    #pragma unroll
    for (int mi = 0; mi < 2; mi++) {
        #pragma unroll
        for (int ni = 0; ni < 4; ni++) {
            const int n = n0 + wn + ni * 8 + cc;
            if (n + 1 < 900) {
                const int dir = (n >= 450);
                const int g   = n - dir * 450;
                const float b0v = dir ? bb[g]     : bf[g];
                const float b1v = dir ? bb[g + 1] : bf[g + 1];
                const size_t dbase = (size_t)dir * BB * TT * G3;
                const int m = m0 + wm + mi * 16 + cr;
                float* p0 = g_gi + dbase + (size_t)m * G3 + g;
                float* p1 = g_gi + dbase + (size_t)(m + 8) * G3 + g;
                p0[0] = acc[mi][ni][0] + b0v;
                p0[1] = acc[mi][ni][1] + b1v;
                p1[0] = acc[mi][ni][2] + b0v;
                p1[1] = acc[mi][ni][3] + b1v;
            }
        }
    }
}

// ==========================================================================
// K2: GRU scan — register-resident weights, SINGLE-PHASE steps (R6 structure:
//     both batches' matvecs interleaved in one thread = 2 independent HFMA2
//     chains for ILP), with chunk-PAIRED flushes (8-long half chains halve the
//     cvt/add overhead) and fast exp-based tanh in the gate.
// ==========================================================================
__global__ void __launch_bounds__(480, 1) gru_scan(
    const float* __restrict__ Whh_f, const float* __restrict__ Whh_b,
    const float* __restrict__ bhh_f, const float* __restrict__ bhh_b)
{
    __shared__ __align__(16) __half hh[2][152];   // fp16 h, 2 batches (+pad)
    __shared__ float hf[304];                     // fp32 master h
    __shared__ float ghm[2][452];                 // gh exchange

    const int tid = threadIdx.x;
    const int dir = blockIdx.x >> 6;
    const int b0  = (blockIdx.x & 63) * 2;

    // ---- one-time: this thread's Whh row -> 76 half2 registers ----
    __half2 w[76];
    float bhv = 0.f;
    if (tid < G3) {
        const float* Whh = (dir ? Whh_b : Whh_f) + tid * HH;
        #pragma unroll
        for (int q = 0; q < 75; q++)
            w[q] = __floats2half2_rn(Whh[2 * q], Whh[2 * q + 1]);
        w[75] = __floats2half2_rn(0.f, 0.f);
        bhv = (dir ? bhh_b : bhh_f)[tid];
    }
    for (int i = tid; i < 2 * 152; i += 480) hh[0][i] = __float2half(0.f);
    if (tid < 300) hf[tid] = 0.f;
    __syncthreads();

    const int nb = tid / HH;     // valid when tid < 300
    const int j  = tid - nb * HH;

    // strided pointers (avoid per-step muls)
    const long dstep = dir ? -(long)G3 : (long)G3;
    const long sstep = dir ? -(long)D2 : (long)D2;
    const int  t0    = dir ? (TT - 1) : 0;
    const float* gip = g_gi + (((size_t)(dir * BB + b0 + nb)) * TT + t0) * G3 + j;
    float*       sqp = g_seq + (((size_t)(b0 + nb)) * TT + t0) * D2 + dir * HH + j;

    for (int s = 0; s < TT; s++) {
        // issue gi loads early; consumed only after the matvec + barrier
        float gir = 0.f, giz = 0.f, gin = 0.f;
        if (tid < 300) {
            gir = gip[0]; giz = gip[HH]; gin = gip[2 * HH];
        }
        if (tid < G3) {
            const uint4* h0 = (const uint4*)hh[0];
            const uint4* h1 = (const uint4*)hh[1];
            float acc0 = 0.f, acc1 = 0.f;
            // 9 chunk-pairs: 8-long half chains, 2 independent chains (A,B)
            #pragma unroll
            for (int cp = 0; cp < 9; cp++) {
                uint4 ha0 = h0[2 * cp];
                uint4 ha1 = h0[2 * cp + 1];
                uint4 hb0 = h1[2 * cp];
                uint4 hb1 = h1[2 * cp + 1];
                const __half2* a0 = (const __half2*)&ha0;
                const __half2* a1 = (const __half2*)&ha1;
                const __half2* b0p = (const __half2*)&hb0;
                const __half2* b1p = (const __half2*)&hb1;
                __half2 s0 = __floats2half2_rn(0.f, 0.f);
                __half2 s1 = s0;
                #pragma unroll
                for (int q = 0; q < 4; q++) {
                    s0 = __hfma2(w[cp * 8 + q], a0[q], s0);
                    s1 = __hfma2(w[cp * 8 + q], b0p[q], s1);
                }
                #pragma unroll
                for (int q = 0; q < 4; q++) {
                    s0 = __hfma2(w[cp * 8 + 4 + q], a1[q], s0);
                    s1 = __hfma2(w[cp * 8 + 4 + q], b1p[q], s1);
                }
                float2 f0 = __half22float2(s0); acc0 += f0.x + f0.y;
                float2 f1 = __half22float2(s1); acc1 += f1.x + f1.y;
            }
            // final chunk (cols 144..151, 4-long chains)
            {
                uint4 ha = h0[18];
                uint4 hb = h1[18];
                const __half2* ap = (const __half2*)&ha;
                const __half2* bp = (const __half2*)&hb;
                __half2 s0 = __floats2half2_rn(0.f, 0.f);
                __half2 s1 = s0;
                #pragma unroll
                for (int q = 0; q < 4; q++) {
                    s0 = __hfma2(w[72 + q], ap[q], s0);
                    s1 = __hfma2(w[72 + q], bp[q], s1);
                }
                float2 f0 = __half22float2(s0); acc0 += f0.x + f0.y;
                float2 f1 = __half22float2(s1); acc1 += f1.x + f1.y;
            }
            ghm[0][tid] = acc0 + bhv;
            ghm[1][tid] = acc1 + bhv;
        }
        __syncthreads();
        if (tid < 300) {
            const float* gh = ghm[nb];
            float r = 1.f / (1.f + __expf(-(gir + gh[j])));
            float z = 1.f / (1.f + __expf(-(giz + gh[HH + j])));
            float u = gin + r * gh[2 * HH + j];
            float e = __expf(-2.f * u);
            float n = __fdividef(2.f, 1.f + e) - 1.f;   // tanh(u), overflow-safe
            float h = hf[tid];
            float hn = (1.f - z) * n + z * h;
            hf[tid] = hn;
            hh[nb][j] = __float2half_rn(hn);
            *sqp = hn;
            gip += dstep;
            sqp += sstep;
        }
        __syncthreads();
    }
    if (tid < 300)
        g_hidden[(b0 + nb) * D2 + dir * HH + j] = hf[tid];
}

// ==========================================================================
// K3a0: ctxA[k][d] = battn[k][d] + attn_context[k,:] . Wattn[k][:300][d]
// ==========================================================================
__global__ void __launch_bounds__(320) ctxA_kernel(
    const float* __restrict__ attn_context, const float* __restrict__ Wattn,
    const float* __restrict__ battn)
{
    const int k = blockIdx.x;
    const int d = threadIdx.x;
    __shared__ float ac[D2];
    if (d < D2) ac[d] = attn_context[k * D2 + d];
    __syncthreads();
    if (d < D2) {
        float acc = battn[k * D2 + d];
        const float* wp = Wattn + (size_t)k * 600 * D2 + d;
        #pragma unroll 1
        for (int c = 0; c < D2; c += 4) {
            float w0 = wp[(size_t)(c + 0) * D2];
            float w1 = wp[(size_t)(c + 1) * D2];
            float w2 = wp[(size_t)(c + 2) * D2];
            float w3 = wp[(size_t)(c + 3) * D2];
            acc += ac[c] * w0 + ac[c + 1] * w1 + ac[c + 2] * w2 + ac[c + 3] * w3;
        }
        g_ctxA[k * D2 + d] = acc;
    }
}

// ==========================================================================
// K3a: context[b][k][d] = tanh(ctxA[k][d] + hidden[b,:] . Wattn[k][300:][d])
// ==========================================================================
__global__ void __launch_bounds__(320) context_kernel(const float* __restrict__ Wattn)
{
    const int k  = blockIdx.x;
    const int b0 = blockIdx.y * 4;
    const int d  = threadIdx.x;
    __shared__ float hid[4 * D2];
    for (int i = threadIdx.x; i < 4 * D2; i += blockDim.x) hid[i] = g_hidden[b0 * D2 + i];
    __syncthreads();
    if (d < D2) {
        float acc[4];
        const float base = g_ctxA[k * D2 + d];
        #pragma unroll
        for (int bb = 0; bb < 4; bb++) acc[bb] = base;
        const float* wp = Wattn + ((size_t)k * 600 + D2) * D2 + d;
        #pragma unroll 1
        for (int jj = 0; jj < D2; jj += 4) {
            float w0 = wp[(size_t)(jj + 0) * D2];
            float w1 = wp[(size_t)(jj + 1) * D2];
            float w2 = wp[(size_t)(jj + 2) * D2];
            float w3 = wp[(size_t)(jj + 3) * D2];
            #pragma unroll
            for (int bb = 0; bb < 4; bb++) {
                acc[bb] += hid[bb * D2 + jj] * w0 + hid[bb * D2 + jj + 1] * w1
                         + hid[bb * D2 + jj + 2] * w2 + hid[bb * D2 + jj + 3] * w3;
            }
        }
        #pragma unroll
        for (int bb = 0; bb < 4; bb++)
            g_context[((size_t)(b0 + bb) * KK + k) * D2 + d] = tanhf(acc[bb]);
    }
}

// ==========================================================================
// K3b: energy[b][t][k] = seq[b,t,:] . context[b,k,:]
// ==========================================================================
__global__ void __launch_bounds__(256) energy_kernel()
{
    const int b = blockIdx.x;
    __shared__ float ctx[KK * 301];
    __shared__ float seq_s[32 * D2];
    const int tid = threadIdx.x;
    for (int i = tid; i < KK * D2; i += 256) {
        int k = i / D2, d = i % D2;
        ctx[k * 301 + d] = g_context[((size_t)b * KK + k) * D2 + d];
    }
    const int tt = tid >> 3, kk = tid & 7;
    for (int t0 = 0; t0 < TT; t0 += 32) {
        __syncthreads();
        for (int i = tid; i < 32 * D2; i += 256)
            seq_s[i] = g_seq[((size_t)b * TT + t0) * D2 + i];
        __syncthreads();
        if (kk < KK) {
            const float* sr = seq_s + tt * D2;
            const float* cr = ctx + kk * 301;
            float e = 0.f;
            #pragma unroll 4
            for (int d = 0; d < D2; d++) e += sr[d] * cr[d];
            g_energy[((size_t)b * TT + t0 + tt) * KK + kk] = e;
        }
    }
}

// ==========================================================================
// K3c: softmax over T per (b,k), in place on g_energy
// ==========================================================================
__global__ void __launch_bounds__(192) softmax_t()
{
    const int b = blockIdx.x;
    const int k = threadIdx.x >> 5;
    const int lane = threadIdx.x & 31;
    float v[16];
    float m = -1e30f;
    #pragma unroll
    for (int i = 0; i < 16; i++) {
        v[i] = g_energy[((size_t)b * TT + lane + i * 32) * KK + k];
        m = fmaxf(m, v[i]);
    }
    #pragma unroll
    for (int o = 16; o; o >>= 1) m = fmaxf(m, __shfl_xor_sync(0xffffffffu, m, o));
    float ssum = 0.f;
    #pragma unroll
    for (int i = 0; i < 16; i++) { v[i] = __expf(v[i] - m); ssum += v[i]; }
    #pragma unroll
    for (int o = 16; o; o >>= 1) ssum += __shfl_xor_sync(0xffffffffu, ssum, o);
    const float inv = 1.f / ssum;
    #pragma unroll
    for (int i = 0; i < 16; i++)
        g_energy[((size_t)b * TT + lane + i * 32) * KK + k] = v[i] * inv;
}

// ==========================================================================
// K3d: pooled[b][k][d] = sum_t seq[b,t,d] * probs[b,t,k]
// ==========================================================================
__global__ void __launch_bounds__(320) pooled_kernel()
{
    const int b = blockIdx.x;
    const int tid = threadIdx.x;
    __shared__ float seq_s[32 * D2];
    __shared__ float pr[32 * 8];
    float acc[KK];
    #pragma unroll
    for (int k = 0; k < KK; k++) acc[k] = 0.f;
    for (int t0 = 0; t0 < TT; t0 += 32) {
        __syncthreads();
        for (int i = tid; i < 32 * D2; i += 320)
            seq_s[i] = g_seq[((size_t)b * TT + t0) * D2 + i];
        for (int i = tid; i < 32 * KK; i += 320) {
            int tt = i / KK, k = i % KK;
            pr[tt * 8 + k] = g_energy[((size_t)b * TT + t0 + tt) * KK + k];
        }
        __syncthreads();
        if (tid < D2) {
            #pragma unroll 4
            for (int tt = 0; tt < 32; tt++) {
                const float sv = seq_s[tt * D2 + tid];
                #pragma unroll
                for (int k = 0; k < KK; k++) acc[k] += sv * pr[tt * 8 + k];
            }
        }
    }
    if (tid < D2) {
        #pragma unroll
        for (int k = 0; k < KK; k++)
            g_pooled[((size_t)b * KK + k) * D2 + tid] = acc[k];
    }
}

// ==========================================================================
// K3e: topic heads + logits + softmax + per-batch reg term
// ==========================================================================
__global__ void __launch_bounds__(128) head_kernel(
    const float* __restrict__ Wtop, const float* __restrict__ btop,
    const float* __restrict__ Wout, const float* __restrict__ bout,
    float* __restrict__ out)
{
    const int b = blockIdx.x;
    const int tid = threadIdx.x;
    __shared__ float pl[KK * D2];
    __shared__ float cx[KK * D2];
    __shared__ float tp[KK * THD];
    __shared__ float lg[CLSN];
    __shared__ float inorm[KK];
    __shared__ float gsq[KK * KK];
    for (int i = tid; i < KK * D2; i += 128) {
        pl[i] = g_pooled[(size_t)b * KK * D2 + i];
        cx[i] = g_context[(size_t)b * KK * D2 + i];
    }
    __syncthreads();
    if (tid < KK * THD) {
        const int k = tid / THD, h = tid % THD;
        float a = btop[tid];
        const float* pk = pl + k * D2;
        for (int d = 0; d < D2; d++)
            a += pk[d] * Wtop[((size_t)k * D2 + d) * THD + h];
        tp[tid] = fmaxf(a, 0.f);
    }
    if (tid >= 120 && tid < 120 + KK) {
        const int k = tid - 120;
        const float* ck = cx + k * D2;
        float s = 0.f;
        for (int d = 0; d < D2; d++) s += ck[d] * ck[d];
        inorm[k] = 1.f / fmaxf(sqrtf(s), 1e-12f);
    }
    __syncthreads();
    if (tid < CLSN) {
        float L = bout[tid];
        for (int i = 0; i < KK * THD; i++) L += tp[i] * Wout[i * CLSN + tid];
        lg[tid] = L;
    }
    if (tid >= 32 && tid < 32 + KK * KK) {
        const int q = tid - 32;
        const int k = q / KK, j = q % KK;
        const float* ck = cx + k * D2;
        const float* cj = cx + j * D2;
        float gdot = 0.f;
        for (int d = 0; d < D2; d++) gdot += ck[d] * cj[d];
        gdot *= inorm[k] * inorm[j];
        const float diff = gdot - (k == j ? 1.f : 0.f);
        gsq[q] = diff * diff;
    }
    __syncthreads();
    if (tid < CLSN) {
        float m = lg[0];
        #pragma unroll
        for (int i = 1; i < CLSN; i++) m = fmaxf(m, lg[i]);
        float ss = 0.f;
        #pragma unroll
        for (int i = 0; i < CLSN; i++) ss += __expf(lg[i] - m);
        out[b * CLSN + tid] = __expf(lg[tid] - m) / ss;
    }
    if (tid == 0) {
        float ssum = 0.f;
        #pragma unroll
        for (int i = 0; i < KK * KK; i++) ssum += gsq[i];
        g_regb[b] = sqrtf(ssum);
    }
}

// ==========================================================================
// K3f: reg = mean_b(g_regb)
// ==========================================================================
__global__ void __launch_bounds__(128) reg_reduce(float* __restrict__ out, int out_size)
{
    __shared__ float sh[128];
    const int tid = threadIdx.x;
    sh[tid] = g_regb[tid];
    __syncthreads();
    for (int o = 64; o; o >>= 1) {
        if (tid < o) sh[tid] += sh[tid + o];
        __syncthreads();
    }
    if (tid == 0) out[out_size - 1] = sh[0] * (1.f / 128.f);
}

// ==========================================================================
extern "C" void kernel_launch(void* const* d_in, const int* in_sizes, int n_in,
                              void* d_out, int out_size)
{
    const float* x            = (const float*)d_in[0];
    const float* Wih_f        = (const float*)d_in[1];
    const float* Whh_f        = (const float*)d_in[2];
    const float* bih_f        = (const float*)d_in[3];
    const float* bhh_f        = (const float*)d_in[4];
    const float* Wih_b        = (const float*)d_in[5];
    const float* Whh_b        = (const float*)d_in[6];
    const float* bih_b        = (const float*)d_in[7];
    const float* bhh_b        = (const float*)d_in[8];
    const float* attn_context = (const float*)d_in[9];
    const float* Wattn        = (const float*)d_in[10];
    const float* battn        = (const float*)d_in[11];
    const float* Wtop         = (const float*)d_in[12];
    const float* btop         = (const float*)d_in[13];
    const float* Wout         = (const float*)d_in[14];
    const float* bout         = (const float*)d_in[15];
    float* out = (float*)d_out;

    const size_t xtot = (size_t)BB * TT * KP;
    cvt_x<<<(unsigned)((xtot + 255) / 256), 256>>>(x);
    cvt_w<<<(NPAD * KP + 255) / 256, 256>>>(Wih_f, Wih_b);
    gi_gemm_mma<<<dim3((BB * TT) / GBM, NPAD / GBN), 256>>>(bih_f, bih_b);
    gru_scan<<<128, 480>>>(Whh_f, Whh_b, bhh_f, bhh_b);
    ctxA_kernel<<<KK, 320>>>(attn_context, Wattn, battn);
    context_kernel<<<dim3(KK, 32), 320>>>(Wattn);
    energy_kernel<<<BB, 256>>>();
    softmax_t<<<BB, 192>>>();
    pooled_kernel<<<BB, 320>>>();
    head_kernel<<<BB, 128>>>(Wtop, btop, Wout, bout, out);
    reg_reduce<<<1, 128>>>(out, out_size);
}

// round 14
// speedup vs baseline: 1.3274x; 1.1299x over previous
#include <cuda_runtime.h>
#include <cuda_fp16.h>
#include <cstdint>
#include <cstddef>

// ---------------- problem constants ----------------
#define BB    128
#define TT    512
#define II    300
#define HH    150
#define G3    450    // 3H
#define D2    300    // 2H
#define KK    6
#define THD   20
#define CLSN  5

#define KP    320    // padded K for fp16 GEMM (300 -> 320)
#define NPAD  960    // padded N (900 -> 960)

// ---------------- device scratch (static, allocation-free) ----------------
__device__ float g_gi[(size_t)2 * BB * TT * G3];    // [dir][b][t][g]
__device__ float g_seq[(size_t)BB * TT * D2];       // [b][t][d]
__device__ float g_hidden[BB * D2];
__device__ float g_ctxA[KK * D2];
__device__ float g_context[BB * KK * D2];
__device__ float g_energy[(size_t)BB * TT * KK];    // energy, then probs in-place
__device__ float g_pooled2[2][BB * KK * D2];        // per-T-half partials
__device__ float g_regb[BB];
__device__ __half g_xh[(size_t)BB * TT * KP];       // fp16 x, K padded
__device__ __half g_wh[(size_t)NPAD * KP];          // fp16 [Wf;Wb], K padded

// ==========================================================================
// K0a/K0b: fp32 -> fp16 conversion (zero-padded K)
// ==========================================================================
__global__ void __launch_bounds__(256) cvt_x(const float* __restrict__ x)
{
    size_t i = (size_t)blockIdx.x * 256 + threadIdx.x;
    if (i >= (size_t)BB * TT * KP) return;
    int col = (int)(i % KP);
    size_t row = i / KP;
    g_xh[i] = (col < II) ? __float2half_rn(x[row * II + col]) : __float2half(0.f);
}

__global__ void __launch_bounds__(256) cvt_w(const float* __restrict__ Wf,
                                             const float* __restrict__ Wb)
{
    int i = blockIdx.x * 256 + threadIdx.x;
    if (i >= NPAD * KP) return;
    int col = i % KP;
    int row = i / KP;
    float v = 0.f;
    if (col < II && row < 900)
        v = (row < 450) ? Wf[row * II + col] : Wb[(row - 450) * II + col];
    g_wh[i] = __float2half_rn(v);
}

// ==========================================================================
// K1: gi GEMM on tensor cores (mma.sync m16n8k16, fp16 in / fp32 accum)
// ==========================================================================
__device__ __forceinline__ uint32_t s2u(const void* p) {
    return (uint32_t)__cvta_generic_to_shared(p);
}

#define LDSM4(R, addr) \
    asm volatile("ldmatrix.sync.aligned.m8n8.x4.shared.b16 {%0,%1,%2,%3}, [%4];" \
        : "=r"((R)[0]), "=r"((R)[1]), "=r"((R)[2]), "=r"((R)[3]) : "r"(addr))

#define MMA16816(C, A, b0, b1) \
    asm volatile("mma.sync.aligned.m16n8k16.row.col.f32.f16.f16.f32 " \
        "{%0,%1,%2,%3},{%4,%5,%6,%7},{%8,%9},{%0,%1,%2,%3};" \
        : "+f"((C)[0]), "+f"((C)[1]), "+f"((C)[2]), "+f"((C)[3]) \
        : "r"((A)[0]), "r"((A)[1]), "r"((A)[2]), "r"((A)[3]), "r"(b0), "r"(b1))

#define GBM 128
#define GBN 64
#define GBK 32
#define SPAD 40      // smem row stride in halves (80B: conflict-free ldmatrix)

__global__ void __launch_bounds__(256) gi_gemm_mma(
    const float* __restrict__ bf, const float* __restrict__ bb)
{
    __shared__ __half As[2][GBM][SPAD];
    __shared__ __half Bs[2][GBN][SPAD];

    const int tid  = threadIdx.x;
    const int m0   = blockIdx.x * GBM;
    const int n0   = blockIdx.y * GBN;
    const int warp = tid >> 5;
    const int lane = tid & 31;
    const int wm   = (warp >> 1) * 32;   // 0,32,64,96
    const int wn   = (warp & 1) * 32;    // 0,32

    const int gr = tid >> 2;            // 0..63
    const int gc = (tid & 3) * 8;       // half offset
    const __half* aP0 = g_xh + (size_t)(m0 + gr) * KP + gc;
    const __half* aP1 = g_xh + (size_t)(m0 + gr + 64) * KP + gc;
    const __half* bP  = g_wh + (size_t)(n0 + gr) * KP + gc;

    const uint32_t aAddr = s2u(&As[0][wm + (lane & 15)][(lane >> 4) * 8]);
    const uint32_t bAddr = s2u(&Bs[0][wn + ((lane >> 4) << 3) + (lane & 7)][((lane >> 3) & 1) * 8]);
    const uint32_t ABUF = GBM * SPAD * 2;   // 10240
    const uint32_t BBUF = GBN * SPAD * 2;   // 5120
    const uint32_t RSTR = SPAD * 2;         // 80 bytes / row

    float acc[2][4][4];
    #pragma unroll
    for (int i = 0; i < 2; i++)
        #pragma unroll
        for (int j = 0; j < 4; j++)
            #pragma unroll
            for (int q = 0; q < 4; q++) acc[i][j][q] = 0.f;

    uint4 ra0 = *(const uint4*)aP0;
    uint4 ra1 = *(const uint4*)aP1;
    uint4 rb  = *(const uint4*)bP;
    *(uint4*)&As[0][gr][gc]      = ra0;
    *(uint4*)&As[0][gr + 64][gc] = ra1;
    *(uint4*)&Bs[0][gr][gc]      = rb;
    __syncthreads();

    const int NKT = KP / GBK;   // 10
    for (int kt = 0; kt < NKT; kt++) {
        const int buf = kt & 1;
        if (kt < NKT - 1) {
            const size_t off = (size_t)(kt + 1) * GBK;
            ra0 = *(const uint4*)(aP0 + off);
            ra1 = *(const uint4*)(aP1 + off);
            rb  = *(const uint4*)(bP + off);
        }
        #pragma unroll
        for (int ks = 0; ks < 2; ks++) {
            uint32_t A0[4], A1[4], B0[4], B1[4];
            const uint32_t ao = aAddr + buf * ABUF + ks * 32;
            const uint32_t bo = bAddr + buf * BBUF + ks * 32;
            LDSM4(A0, ao);
            LDSM4(A1, ao + 16 * RSTR);
            LDSM4(B0, bo);
            LDSM4(B1, bo + 16 * RSTR);
            MMA16816(acc[0][0], A0, B0[0], B0[1]);
            MMA16816(acc[0][1], A0, B0[2], B0[3]);
            MMA16816(acc[0][2], A0, B1[0], B1[1]);
            MMA16816(acc[0][3], A0, B1[2], B1[3]);
            MMA16816(acc[1][0], A1, B0[0], B0[1]);
            MMA16816(acc[1][1], A1, B0[2], B0[3]);
            MMA16816(acc[1][2], A1, B1[0], B1[1]);
            MMA16816(acc[1][3], A1, B1[2], B1[3]);
        }
        if (kt < NKT - 1) {
            const int nb = buf ^ 1;
            *(uint4*)&As[nb][gr][gc]      = ra0;
            *(uint4*)&As[nb][gr + 64][gc] = ra1;
            *(uint4*)&Bs[nb][gr][gc]      = rb;
        }
        __syncthreads();
    }

    // epilogue: scatter to g_gi with bias
    const int cr = lane >> 2;           // row within 8
    const int cc = (lane & 3) * 2;      // col pair
    #pragma unroll
    for (int mi = 0; mi < 2; mi++) {
        #pragma unroll
        for (int ni = 0; ni < 4; ni++) {
            const int n = n0 + wn + ni * 8 + cc;
            if (n + 1 < 900) {
                const int dir = (n >= 450);
                const int g   = n - dir * 450;
                const float b0v = dir ? bb[g]     : bf[g];
                const float b1v = dir ? bb[g + 1] : bf[g + 1];
                const size_t dbase = (size_t)dir * BB * TT * G3;
                const int m = m0 + wm + mi * 16 + cr;
                float* p0 = g_gi + dbase + (size_t)m * G3 + g;
                float* p1 = g_gi + dbase + (size_t)(m + 8) * G3 + g;
                p0[0] = acc[mi][ni][0] + b0v;
                p0[1] = acc[mi][ni][1] + b1v;
                p1[0] = acc[mi][ni][2] + b0v;
                p1[1] = acc[mi][ni][3] + b1v;
            }
        }
    }
}

// ==========================================================================
// K2: GRU scan — register-resident weights, single-phase steps with two
//     independent HFMA2 chains (batches A,B), 16-long half chains
//     (5 flushes per batch), fast MUFU-based gate.
// ==========================================================================
__global__ void __launch_bounds__(480, 1) gru_scan(
    const float* __restrict__ Whh_f, const float* __restrict__ Whh_b,
    const float* __restrict__ bhh_f, const float* __restrict__ bhh_b)
{
    __shared__ __align__(16) __half hh[2][152];   // fp16 h, 2 batches (+pad)
    __shared__ float hf[304];                     // fp32 master h
    __shared__ float ghm[2][452];                 // gh exchange

    const int tid = threadIdx.x;
    const int dir = blockIdx.x >> 6;
    const int b0  = (blockIdx.x & 63) * 2;

    // ---- one-time: this thread's Whh row -> 76 half2 registers ----
    __half2 w[76];
    float bhv = 0.f;
    if (tid < G3) {
        const float* Whh = (dir ? Whh_b : Whh_f) + tid * HH;
        #pragma unroll
        for (int q = 0; q < 75; q++)
            w[q] = __floats2half2_rn(Whh[2 * q], Whh[2 * q + 1]);
        w[75] = __floats2half2_rn(0.f, 0.f);
        bhv = (dir ? bhh_b : bhh_f)[tid];
    }
    for (int i = tid; i < 2 * 152; i += 480) hh[0][i] = __float2half(0.f);
    if (tid < 300) hf[tid] = 0.f;
    __syncthreads();

    const int nb = tid / HH;     // valid when tid < 300
    const int j  = tid - nb * HH;

    // strided pointers (avoid per-step muls)
    const long dstep = dir ? -(long)G3 : (long)G3;
    const long sstep = dir ? -(long)D2 : (long)D2;
    const int  t0    = dir ? (TT - 1) : 0;
    const float* gip = g_gi + (((size_t)(dir * BB + b0 + nb)) * TT + t0) * G3 + j;
    float*       sqp = g_seq + (((size_t)(b0 + nb)) * TT + t0) * D2 + dir * HH + j;

    for (int s = 0; s < TT; s++) {
        // issue gi loads early; consumed only after the matvec + barrier
        float gir = 0.f, giz = 0.f, gin = 0.f;
        if (tid < 300) {
            gir = gip[0]; giz = gip[HH]; gin = gip[2 * HH];
        }
        if (tid < G3) {
            const uint4* h0 = (const uint4*)hh[0];
            const uint4* h1 = (const uint4*)hh[1];
            float acc0 = 0.f, acc1 = 0.f;
            // 4 super-chunks: 16-long half chains, 2 independent chains (A,B)
            #pragma unroll
            for (int sc = 0; sc < 4; sc++) {
                __half2 s0 = __floats2half2_rn(0.f, 0.f);
                __half2 s1 = s0;
                #pragma unroll
                for (int hp = 0; hp < 2; hp++) {
                    uint4 ha0 = h0[sc * 4 + hp * 2];
                    uint4 ha1 = h0[sc * 4 + hp * 2 + 1];
                    uint4 hb0 = h1[sc * 4 + hp * 2];
                    uint4 hb1 = h1[sc * 4 + hp * 2 + 1];
                    const __half2* a0  = (const __half2*)&ha0;
                    const __half2* a1  = (const __half2*)&ha1;
                    const __half2* b0p = (const __half2*)&hb0;
                    const __half2* b1p = (const __half2*)&hb1;
                    #pragma unroll
                    for (int q = 0; q < 4; q++) {
                        s0 = __hfma2(w[sc * 16 + hp * 8 + q], a0[q], s0);
                        s1 = __hfma2(w[sc * 16 + hp * 8 + q], b0p[q], s1);
                    }
                    #pragma unroll
                    for (int q = 0; q < 4; q++) {
                        s0 = __hfma2(w[sc * 16 + hp * 8 + 4 + q], a1[q], s0);
                        s1 = __hfma2(w[sc * 16 + hp * 8 + 4 + q], b1p[q], s1);
                    }
                }
                float2 f0 = __half22float2(s0); acc0 += f0.x + f0.y;
                float2 f1 = __half22float2(s1); acc1 += f1.x + f1.y;
            }
            // tail: 12 half2 (w[64..75], h uint4 16..18)
            {
                __half2 s0 = __floats2half2_rn(0.f, 0.f);
                __half2 s1 = s0;
                uint4 ha0 = h0[16]; uint4 ha1 = h0[17];
                uint4 hb0 = h1[16]; uint4 hb1 = h1[17];
                const __half2* a0  = (const __half2*)&ha0;
                const __half2* a1  = (const __half2*)&ha1;
                const __half2* b0p = (const __half2*)&hb0;
                const __half2* b1p = (const __half2*)&hb1;
                #pragma unroll
                for (int q = 0; q < 4; q++) {
                    s0 = __hfma2(w[64 + q], a0[q], s0);
                    s1 = __hfma2(w[64 + q], b0p[q], s1);
                }
                #pragma unroll
                for (int q = 0; q < 4; q++) {
                    s0 = __hfma2(w[68 + q], a1[q], s0);
                    s1 = __hfma2(w[68 + q], b1p[q], s1);
                }
                uint4 ha2 = h0[18]; uint4 hb2 = h1[18];
                const __half2* a2 = (const __half2*)&ha2;
                const __half2* b2 = (const __half2*)&hb2;
                #pragma unroll
                for (int q = 0; q < 4; q++) {
                    s0 = __hfma2(w[72 + q], a2[q], s0);
                    s1 = __hfma2(w[72 + q], b2[q], s1);
                }
                float2 f0 = __half22float2(s0); acc0 += f0.x + f0.y;
                float2 f1 = __half22float2(s1); acc1 += f1.x + f1.y;
            }
            ghm[0][tid] = acc0 + bhv;
            ghm[1][tid] = acc1 + bhv;
        }
        __syncthreads();
        if (tid < 300) {
            const float* gh = ghm[nb];
            float r = __fdividef(1.f, 1.f + __expf(-(gir + gh[j])));
            float z = __fdividef(1.f, 1.f + __expf(-(giz + gh[HH + j])));
            float u = gin + r * gh[2 * HH + j];
            float e = __expf(-2.f * u);
            float n = __fdividef(2.f, 1.f + e) - 1.f;   // tanh(u), overflow-safe
            float h = hf[tid];
            float hn = (1.f - z) * n + z * h;
            hf[tid] = hn;
            hh[nb][j] = __float2half_rn(hn);
            *sqp = hn;
            gip += dstep;
            sqp += sstep;
        }
        __syncthreads();
    }
    if (tid < 300)
        g_hidden[(b0 + nb) * D2 + dir * HH + j] = hf[tid];
}

// ==========================================================================
// K3a0: ctxA[k][d] = battn[k][d] + attn_context[k,:] . Wattn[k][:300][d]
// ==========================================================================
__global__ void __launch_bounds__(320) ctxA_kernel(
    const float* __restrict__ attn_context, const float* __restrict__ Wattn,
    const float* __restrict__ battn)
{
    const int k = blockIdx.x;
    const int d = threadIdx.x;
    __shared__ float ac[D2];
    if (d < D2) ac[d] = attn_context[k * D2 + d];
    __syncthreads();
    if (d < D2) {
        float acc = battn[k * D2 + d];
        const float* wp = Wattn + (size_t)k * 600 * D2 + d;
        #pragma unroll 1
        for (int c = 0; c < D2; c += 4) {
            float w0 = wp[(size_t)(c + 0) * D2];
            float w1 = wp[(size_t)(c + 1) * D2];
            float w2 = wp[(size_t)(c + 2) * D2];
            float w3 = wp[(size_t)(c + 3) * D2];
            acc += ac[c] * w0 + ac[c + 1] * w1 + ac[c + 2] * w2 + ac[c + 3] * w3;
        }
        g_ctxA[k * D2 + d] = acc;
    }
}

// ==========================================================================
// K3a: context[b][k][d] = tanh(ctxA[k][d] + hidden[b,:] . Wattn[k][300:][d])
// ==========================================================================
__global__ void __launch_bounds__(320) context_kernel(const float* __restrict__ Wattn)
{
    const int k  = blockIdx.x;
    const int b0 = blockIdx.y * 4;
    const int d  = threadIdx.x;
    __shared__ float hid[4 * D2];
    for (int i = threadIdx.x; i < 4 * D2; i += blockDim.x) hid[i] = g_hidden[b0 * D2 + i];
    __syncthreads();
    if (d < D2) {
        float acc[4];
        const float base = g_ctxA[k * D2 + d];
        #pragma unroll
        for (int bb = 0; bb < 4; bb++) acc[bb] = base;
        const float* wp = Wattn + ((size_t)k * 600 + D2) * D2 + d;
        #pragma unroll 1
        for (int jj = 0; jj < D2; jj += 4) {
            float w0 = wp[(size_t)(jj + 0) * D2];
            float w1 = wp[(size_t)(jj + 1) * D2];
            float w2 = wp[(size_t)(jj + 2) * D2];
            float w3 = wp[(size_t)(jj + 3) * D2];
            #pragma unroll
            for (int bb = 0; bb < 4; bb++) {
                acc[bb] += hid[bb * D2 + jj] * w0 + hid[bb * D2 + jj + 1] * w1
                         + hid[bb * D2 + jj + 2] * w2 + hid[bb * D2 + jj + 3] * w3;
            }
        }
        #pragma unroll
        for (int bb = 0; bb < 4; bb++)
            g_context[((size_t)(b0 + bb) * KK + k) * D2 + d] = tanhf(acc[bb]);
    }
}

// ==========================================================================
// K3b: energy[b][t][k] = seq[b,t,:] . context[b,k,:]   — grid (B, 2 T-halves)
// ==========================================================================
__global__ void __launch_bounds__(256) energy_kernel()
{
    const int b  = blockIdx.x;
    const int th = blockIdx.y;          // T half
    __shared__ float ctx[KK * 301];
    __shared__ float seq_s[32 * D2];
    const int tid = threadIdx.x;
    for (int i = tid; i < KK * D2; i += 256) {
        int k = i / D2, d = i % D2;
        ctx[k * 301 + d] = g_context[((size_t)b * KK + k) * D2 + d];
    }
    const int tt = tid >> 3, kk = tid & 7;
    const int tbeg = th * 256;
    for (int t0 = tbeg; t0 < tbeg + 256; t0 += 32) {
        __syncthreads();
        for (int i = tid; i < 32 * D2; i += 256)
            seq_s[i] = g_seq[((size_t)b * TT + t0) * D2 + i];
        __syncthreads();
        if (kk < KK) {
            const float* sr = seq_s + tt * D2;
            const float* cr = ctx + kk * 301;
            float e = 0.f;
            #pragma unroll 4
            for (int d = 0; d < D2; d++) e += sr[d] * cr[d];
            g_energy[((size_t)b * TT + t0 + tt) * KK + kk] = e;
        }
    }
}

// ==========================================================================
// K3c: softmax over T per (b,k), in place on g_energy
// ==========================================================================
__global__ void __launch_bounds__(192) softmax_t()
{
    const int b = blockIdx.x;
    const int k = threadIdx.x >> 5;
    const int lane = threadIdx.x & 31;
    float v[16];
    float m = -1e30f;
    #pragma unroll
    for (int i = 0; i < 16; i++) {
        v[i] = g_energy[((size_t)b * TT + lane + i * 32) * KK + k];
        m = fmaxf(m, v[i]);
    }
    #pragma unroll
    for (int o = 16; o; o >>= 1) m = fmaxf(m, __shfl_xor_sync(0xffffffffu, m, o));
    float ssum = 0.f;
    #pragma unroll
    for (int i = 0; i < 16; i++) { v[i] = __expf(v[i] - m); ssum += v[i]; }
    #pragma unroll
    for (int o = 16; o; o >>= 1) ssum += __shfl_xor_sync(0xffffffffu, ssum, o);
    const float inv = 1.f / ssum;
    #pragma unroll
    for (int i = 0; i < 16; i++)
        g_energy[((size_t)b * TT + lane + i * 32) * KK + k] = v[i] * inv;
}

// ==========================================================================
// K3d: pooled partial[b][k][d] over T half  — grid (B, 2)
// ==========================================================================
__global__ void __launch_bounds__(320) pooled_kernel()
{
    const int b  = blockIdx.x;
    const int th = blockIdx.y;
    const int tid = threadIdx.x;
    __shared__ float seq_s[32 * D2];
    __shared__ float pr[32 * 8];
    float acc[KK];
    #pragma unroll
    for (int k = 0; k < KK; k++) acc[k] = 0.f;
    const int tbeg = th * 256;
    for (int t0 = tbeg; t0 < tbeg + 256; t0 += 32) {
        __syncthreads();
        for (int i = tid; i < 32 * D2; i += 320)
            seq_s[i] = g_seq[((size_t)b * TT + t0) * D2 + i];
        for (int i = tid; i < 32 * KK; i += 320) {
            int tt = i / KK, k = i % KK;
            pr[tt * 8 + k] = g_energy[((size_t)b * TT + t0 + tt) * KK + k];
        }
        __syncthreads();
        if (tid < D2) {
            #pragma unroll 4
            for (int tt = 0; tt < 32; tt++) {
                const float sv = seq_s[tt * D2 + tid];
                #pragma unroll
                for (int k = 0; k < KK; k++) acc[k] += sv * pr[tt * 8 + k];
            }
        }
    }
    if (tid < D2) {
        #pragma unroll
        for (int k = 0; k < KK; k++)
            g_pooled2[th][((size_t)b * KK + k) * D2 + tid] = acc[k];
    }
}

// ==========================================================================
// K3e: topic heads + logits + softmax + per-batch reg term
// ==========================================================================
__global__ void __launch_bounds__(128) head_kernel(
    const float* __restrict__ Wtop, const float* __restrict__ btop,
    const float* __restrict__ Wout, const float* __restrict__ bout,
    float* __restrict__ out)
{
    const int b = blockIdx.x;
    const int tid = threadIdx.x;
    __shared__ float pl[KK * D2];
    __shared__ float cx[KK * D2];
    __shared__ float tp[KK * THD];
    __shared__ float lg[CLSN];
    __shared__ float inorm[KK];
    __shared__ float gsq[KK * KK];
    for (int i = tid; i < KK * D2; i += 128) {
        pl[i] = g_pooled2[0][(size_t)b * KK * D2 + i]
              + g_pooled2[1][(size_t)b * KK * D2 + i];
        cx[i] = g_context[(size_t)b * KK * D2 + i];
    }
    __syncthreads();
    if (tid < KK * THD) {
        const int k = tid / THD, h = tid % THD;
        float a = btop[tid];
        const float* pk = pl + k * D2;
        for (int d = 0; d < D2; d++)
            a += pk[d] * Wtop[((size_t)k * D2 + d) * THD + h];
        tp[tid] = fmaxf(a, 0.f);
    }
    if (tid >= 120 && tid < 120 + KK) {
        const int k = tid - 120;
        const float* ck = cx + k * D2;
        float s = 0.f;
        for (int d = 0; d < D2; d++) s += ck[d] * ck[d];
        inorm[k] = 1.f / fmaxf(sqrtf(s), 1e-12f);
    }
    __syncthreads();
    if (tid < CLSN) {
        float L = bout[tid];
        for (int i = 0; i < KK * THD; i++) L += tp[i] * Wout[i * CLSN + tid];
        lg[tid] = L;
    }
    if (tid >= 32 && tid < 32 + KK * KK) {
        const int q = tid - 32;
        const int k = q / KK, j = q % KK;
        const float* ck = cx + k * D2;
        const float* cj = cx + j * D2;
        float gdot = 0.f;
        for (int d = 0; d < D2; d++) gdot += ck[d] * cj[d];
        gdot *= inorm[k] * inorm[j];
        const float diff = gdot - (k == j ? 1.f : 0.f);
        gsq[q] = diff * diff;
    }
    __syncthreads();
    if (tid < CLSN) {
        float m = lg[0];
        #pragma unroll
        for (int i = 1; i < CLSN; i++) m = fmaxf(m, lg[i]);
        float ss = 0.f;
        #pragma unroll
        for (int i = 0; i < CLSN; i++) ss += __expf(lg[i] - m);
        out[b * CLSN + tid] = __expf(lg[tid] - m) / ss;
    }
    if (tid == 0) {
        float ssum = 0.f;
        #pragma unroll
        for (int i = 0; i < KK * KK; i++) ssum += gsq[i];
        g_regb[b] = sqrtf(ssum);
    }
}

// ==========================================================================
// K3f: reg = mean_b(g_regb)
// ==========================================================================
__global__ void __launch_bounds__(128) reg_reduce(float* __restrict__ out, int out_size)
{
    __shared__ float sh[128];
    const int tid = threadIdx.x;
    sh[tid] = g_regb[tid];
    __syncthreads();
    for (int o = 64; o; o >>= 1) {
        if (tid < o) sh[tid] += sh[tid + o];
        __syncthreads();
    }
    if (tid == 0) out[out_size - 1] = sh[0] * (1.f / 128.f);
}

// ==========================================================================
extern "C" void kernel_launch(void* const* d_in, const int* in_sizes, int n_in,
                              void* d_out, int out_size)
{
    const float* x            = (const float*)d_in[0];
    const float* Wih_f        = (const float*)d_in[1];
    const float* Whh_f        = (const float*)d_in[2];
    const float* bih_f        = (const float*)d_in[3];
    const float* bhh_f        = (const float*)d_in[4];
    const float* Wih_b        = (const float*)d_in[5];
    const float* Whh_b        = (const float*)d_in[6];
    const float* bih_b        = (const float*)d_in[7];
    const float* bhh_b        = (const float*)d_in[8];
    const float* attn_context = (const float*)d_in[9];
    const float* Wattn        = (const float*)d_in[10];
    const float* battn        = (const float*)d_in[11];
    const float* Wtop         = (const float*)d_in[12];
    const float* btop         = (const float*)d_in[13];
    const float* Wout         = (const float*)d_in[14];
    const float* bout         = (const float*)d_in[15];
    float* out = (float*)d_out;

    const size_t xtot = (size_t)BB * TT * KP;
    cvt_x<<<(unsigned)((xtot + 255) / 256), 256>>>(x);
    cvt_w<<<(NPAD * KP + 255) / 256, 256>>>(Wih_f, Wih_b);
    gi_gemm_mma<<<dim3((BB * TT) / GBM, NPAD / GBN), 256>>>(bih_f, bih_b);
    gru_scan<<<128, 480>>>(Whh_f, Whh_b, bhh_f, bhh_b);
    ctxA_kernel<<<KK, 320>>>(attn_context, Wattn, battn);
    context_kernel<<<dim3(KK, 32), 320>>>(Wattn);
    energy_kernel<<<dim3(BB, 2), 256>>>();
    softmax_t<<<BB, 192>>>();
    pooled_kernel<<<dim3(BB, 2), 320>>>();
    head_kernel<<<BB, 128>>>(Wtop, btop, Wout, bout, out);
    reg_reduce<<<1, 128>>>(out, out_size);
}

// round 15
// speedup vs baseline: 1.3899x; 1.0471x over previous
#include <cuda_runtime.h>
#include <cuda_fp16.h>
#include <cstdint>
#include <cstddef>

// ---------------- problem constants ----------------
#define BB    128
#define TT    512
#define II    300
#define HH    150
#define G3    450    // 3H
#define G3P   464    // padded g_gi row (1856B, 32B-aligned)
#define D2    300    // 2H
#define KK    6
#define THD   20
#define CLSN  5

#define KP    320    // padded K for fp16 GEMM (300 -> 320)
#define NPAD  960    // padded N (900 -> 960)

// ---------------- device scratch (static, allocation-free) ----------------
__device__ float g_gi[(size_t)2 * BB * TT * G3P];   // [dir][b][t][g padded]
__device__ float g_seq[(size_t)BB * TT * D2];       // [b][t][d]
__device__ float g_hidden[BB * D2];
__device__ float g_ctxA[KK * D2];
__device__ float g_context[BB * KK * D2];
__device__ float g_energy[(size_t)BB * TT * KK];    // energy, then probs in-place
__device__ float g_pooled2[2][BB * KK * D2];        // per-T-half partials
__device__ float g_regb[BB];
__device__ __half g_xh[(size_t)BB * TT * KP];       // fp16 x, K padded
__device__ __half g_wh[(size_t)NPAD * KP];          // fp16 [Wf;Wb], K padded

// ==========================================================================
// K0a/K0b: fp32 -> fp16 conversion (zero-padded K)
// ==========================================================================
__global__ void __launch_bounds__(256) cvt_x(const float* __restrict__ x)
{
    size_t i = (size_t)blockIdx.x * 256 + threadIdx.x;
    if (i >= (size_t)BB * TT * KP) return;
    int col = (int)(i % KP);
    size_t row = i / KP;
    g_xh[i] = (col < II) ? __float2half_rn(x[row * II + col]) : __float2half(0.f);
}

__global__ void __launch_bounds__(256) cvt_w(const float* __restrict__ Wf,
                                             const float* __restrict__ Wb)
{
    int i = blockIdx.x * 256 + threadIdx.x;
    if (i >= NPAD * KP) return;
    int col = i % KP;
    int row = i / KP;
    float v = 0.f;
    if (col < II && row < 900)
        v = (row < 450) ? Wf[row * II + col] : Wb[(row - 450) * II + col];
    g_wh[i] = __float2half_rn(v);
}

// ==========================================================================
// K1: gi GEMM, persistent-A version.
//     One CTA per 128-row m-block. A (128x320 fp16) lives in smem for the
//     whole kernel; internal loop over 15 n-blocks of 64 with double-buffered
//     B tiles. mma.sync m16n8k16, 8 warps (4m x 2n), warp tile 32x32.
// ==========================================================================
__device__ __forceinline__ uint32_t s2u(const void* p) {
    return (uint32_t)__cvta_generic_to_shared(p);
}

#define LDSM4(R, addr) \
    asm volatile("ldmatrix.sync.aligned.m8n8.x4.shared.b16 {%0,%1,%2,%3}, [%4];" \
        : "=r"((R)[0]), "=r"((R)[1]), "=r"((R)[2]), "=r"((R)[3]) : "r"(addr))

#define MMA16816(C, A, b0, b1) \
    asm volatile("mma.sync.aligned.m16n8k16.row.col.f32.f16.f16.f32 " \
        "{%0,%1,%2,%3},{%4,%5,%6,%7},{%8,%9},{%0,%1,%2,%3};" \
        : "+f"((C)[0]), "+f"((C)[1]), "+f"((C)[2]), "+f"((C)[3]) \
        : "r"((A)[0]), "r"((A)[1]), "r"((A)[2]), "r"((A)[3]), "r"(b0), "r"(b1))

#define GBM 128
#define GBN 64
#define ASTR 328                     // A smem row stride in halves (656B, odd 16B units)
#define ABYTES (GBM * ASTR * 2)      // 83968
#define BSTR 40                      // B smem row stride in halves (80B)
#define BBUF_B (GBN * BSTR * 2)      // 5120 bytes per B buffer
#define GI_SMEM (ABYTES + 2 * BBUF_B)   // 94208

__global__ void __launch_bounds__(256) gi_gemm_mma(
    const float* __restrict__ bf, const float* __restrict__ bb)
{
    extern __shared__ __align__(16) unsigned char sm_raw[];
    __half* Asm = (__half*)sm_raw;                    // [128][ASTR]
    __half* Bsm = (__half*)(sm_raw + ABYTES);         // [2][64][BSTR]

    const int tid  = threadIdx.x;
    const int m0   = blockIdx.x * GBM;
    const int warp = tid >> 5;
    const int lane = tid & 31;
    const int wm   = (warp >> 1) * 32;   // 0,32,64,96
    const int wn   = (warp & 1) * 32;    // 0,32

    // ---- load A once: 128 rows x 320 halves = 5120 uint4 ----
    {
        const int nU = (GBM * KP) / 8;   // 5120
        for (int i = tid; i < nU; i += 256) {
            int row = i / (KP / 8);
            int c8  = (i % (KP / 8)) * 8;
            uint4 v = *(const uint4*)(g_xh + (size_t)(m0 + row) * KP + c8);
            *(uint4*)(Asm + row * ASTR + c8) = v;
        }
    }

    // B global-load mapping: 64 rows x 32 halves per tile, 1 uint4/thread
    const int gr = tid >> 2;            // 0..63
    const int gc = (tid & 3) * 8;       // half offset

    // ldmatrix addresses
    const uint32_t aAddr = s2u(Asm + (wm + (lane & 15)) * ASTR + (lane >> 4) * 8);
    const uint32_t bAddr = s2u(Bsm + (wn + ((lane >> 4) << 3) + (lane & 7)) * BSTR
                               + ((lane >> 3) & 1) * 8);

    float acc[2][4][4];
    #pragma unroll
    for (int i = 0; i < 2; i++)
        #pragma unroll
        for (int j = 0; j < 4; j++)
            #pragma unroll
            for (int q = 0; q < 4; q++) acc[i][j][q] = 0.f;

    // prologue: B tile (n=0, kt=0)
    uint4 rb = *(const uint4*)(g_wh + (size_t)gr * KP + gc);
    *(uint4*)(Bsm + gr * BSTR + gc) = rb;
    __syncthreads();

    const int cr = lane >> 2;           // row within 8
    const int cc = (lane & 3) * 2;      // col pair

    const int NIT = 15 * 10;            // n-blocks x kt
    for (int it = 0; it < NIT; it++) {
        const int buf = it & 1;
        const int kt  = it % 10;
        if (it < NIT - 1) {
            const int nn = (it + 1) / 10;
            const int kk = (it + 1) % 10;
            rb = *(const uint4*)(g_wh + (size_t)(nn * 64 + gr) * KP + kk * 32 + gc);
        }
        #pragma unroll
        for (int ks = 0; ks < 2; ks++) {
            uint32_t A0[4], A1[4], B0[4], B1[4];
            const uint32_t ao = aAddr + kt * 64 + ks * 32;
            const uint32_t bo = bAddr + buf * BBUF_B + ks * 32;
            LDSM4(A0, ao);
            LDSM4(A1, ao + 16 * (ASTR * 2));
            LDSM4(B0, bo);
            LDSM4(B1, bo + 16 * (BSTR * 2));
            MMA16816(acc[0][0], A0, B0[0], B0[1]);
            MMA16816(acc[0][1], A0, B0[2], B0[3]);
            MMA16816(acc[0][2], A0, B1[0], B1[1]);
            MMA16816(acc[0][3], A0, B1[2], B1[3]);
            MMA16816(acc[1][0], A1, B0[0], B0[1]);
            MMA16816(acc[1][1], A1, B0[2], B0[3]);
            MMA16816(acc[1][2], A1, B1[0], B1[1]);
            MMA16816(acc[1][3], A1, B1[2], B1[3]);
        }
        if (kt == 9) {
            // epilogue for this n-block: scatter to padded g_gi with bias
            const int n0 = (it / 10) * GBN;
            #pragma unroll
            for (int mi = 0; mi < 2; mi++) {
                #pragma unroll
                for (int ni = 0; ni < 4; ni++) {
                    const int n = n0 + wn + ni * 8 + cc;
                    if (n + 1 < 900) {
                        const int dir = (n >= 450);
                        const int g   = n - dir * 450;
                        const float b0v = dir ? bb[g]     : bf[g];
                        const float b1v = dir ? bb[g + 1] : bf[g + 1];
                        const size_t dbase = (size_t)dir * BB * TT * G3P;
                        const int m = m0 + wm + mi * 16 + cr;
                        float* p0 = g_gi + dbase + (size_t)m * G3P + g;
                        float* p1 = g_gi + dbase + (size_t)(m + 8) * G3P + g;
                        p0[0] = acc[mi][ni][0] + b0v;
                        p0[1] = acc[mi][ni][1] + b1v;
                        p1[0] = acc[mi][ni][2] + b0v;
                        p1[1] = acc[mi][ni][3] + b1v;
                    }
                }
            }
            #pragma unroll
            for (int i = 0; i < 2; i++)
                #pragma unroll
                for (int j = 0; j < 4; j++)
                    #pragma unroll
                    for (int q = 0; q < 4; q++) acc[i][j][q] = 0.f;
        }
        if (it < NIT - 1)
            *(uint4*)(Bsm + (buf ^ 1) * (BBUF_B / 2) * 0 + (buf ^ 1) * GBN * BSTR + gr * BSTR + gc) = rb;
        __syncthreads();
    }
}

// ==========================================================================
// K2: GRU scan — register-resident weights, single-phase steps with two
//     independent HFMA2 chains (batches A,B), 16-long half chains, fast gate.
// ==========================================================================
__global__ void __launch_bounds__(480, 1) gru_scan(
    const float* __restrict__ Whh_f, const float* __restrict__ Whh_b,
    const float* __restrict__ bhh_f, const float* __restrict__ bhh_b)
{
    __shared__ __align__(16) __half hh[2][152];   // fp16 h, 2 batches (+pad)
    __shared__ float hf[304];                     // fp32 master h
    __shared__ float ghm[2][452];                 // gh exchange

    const int tid = threadIdx.x;
    const int dir = blockIdx.x >> 6;
    const int b0  = (blockIdx.x & 63) * 2;

    // ---- one-time: this thread's Whh row -> 76 half2 registers ----
    __half2 w[76];
    float bhv = 0.f;
    if (tid < G3) {
        const float* Whh = (dir ? Whh_b : Whh_f) + tid * HH;
        #pragma unroll
        for (int q = 0; q < 75; q++)
            w[q] = __floats2half2_rn(Whh[2 * q], Whh[2 * q + 1]);
        w[75] = __floats2half2_rn(0.f, 0.f);
        bhv = (dir ? bhh_b : bhh_f)[tid];
    }
    for (int i = tid; i < 2 * 152; i += 480) hh[0][i] = __float2half(0.f);
    if (tid < 300) hf[tid] = 0.f;
    __syncthreads();

    const int nb = tid / HH;     // valid when tid < 300
    const int j  = tid - nb * HH;

    // strided pointers (avoid per-step muls)
    const long dstep = dir ? -(long)G3P : (long)G3P;
    const long sstep = dir ? -(long)D2 : (long)D2;
    const int  t0    = dir ? (TT - 1) : 0;
    const float* gip = g_gi + (((size_t)(dir * BB + b0 + nb)) * TT + t0) * G3P + j;
    float*       sqp = g_seq + (((size_t)(b0 + nb)) * TT + t0) * D2 + dir * HH + j;

    for (int s = 0; s < TT; s++) {
        // issue gi loads early; consumed only after the matvec + barrier
        float gir = 0.f, giz = 0.f, gin = 0.f;
        if (tid < 300) {
            gir = gip[0]; giz = gip[HH]; gin = gip[2 * HH];
        }
        if (tid < G3) {
            const uint4* h0 = (const uint4*)hh[0];
            const uint4* h1 = (const uint4*)hh[1];
            float acc0 = 0.f, acc1 = 0.f;
            // 4 super-chunks: 16-long half chains, 2 independent chains (A,B)
            #pragma unroll
            for (int sc = 0; sc < 4; sc++) {
                __half2 s0 = __floats2half2_rn(0.f, 0.f);
                __half2 s1 = s0;
                #pragma unroll
                for (int hp = 0; hp < 2; hp++) {
                    uint4 ha0 = h0[sc * 4 + hp * 2];
                    uint4 ha1 = h0[sc * 4 + hp * 2 + 1];
                    uint4 hb0 = h1[sc * 4 + hp * 2];
                    uint4 hb1 = h1[sc * 4 + hp * 2 + 1];
                    const __half2* a0  = (const __half2*)&ha0;
                    const __half2* a1  = (const __half2*)&ha1;
                    const __half2* b0p = (const __half2*)&hb0;
                    const __half2* b1p = (const __half2*)&hb1;
                    #pragma unroll
                    for (int q = 0; q < 4; q++) {
                        s0 = __hfma2(w[sc * 16 + hp * 8 + q], a0[q], s0);
                        s1 = __hfma2(w[sc * 16 + hp * 8 + q], b0p[q], s1);
                    }
                    #pragma unroll
                    for (int q = 0; q < 4; q++) {
                        s0 = __hfma2(w[sc * 16 + hp * 8 + 4 + q], a1[q], s0);
                        s1 = __hfma2(w[sc * 16 + hp * 8 + 4 + q], b1p[q], s1);
                    }
                }
                float2 f0 = __half22float2(s0); acc0 += f0.x + f0.y;
                float2 f1 = __half22float2(s1); acc1 += f1.x + f1.y;
            }
            // tail: 12 half2 (w[64..75], h uint4 16..18)
            {
                __half2 s0 = __floats2half2_rn(0.f, 0.f);
                __half2 s1 = s0;
                uint4 ha0 = h0[16]; uint4 ha1 = h0[17];
                uint4 hb0 = h1[16]; uint4 hb1 = h1[17];
                const __half2* a0  = (const __half2*)&ha0;
                const __half2* a1  = (const __half2*)&ha1;
                const __half2* b0p = (const __half2*)&hb0;
                const __half2* b1p = (const __half2*)&hb1;
                #pragma unroll
                for (int q = 0; q < 4; q++) {
                    s0 = __hfma2(w[64 + q], a0[q], s0);
                    s1 = __hfma2(w[64 + q], b0p[q], s1);
                }
                #pragma unroll
                for (int q = 0; q < 4; q++) {
                    s0 = __hfma2(w[68 + q], a1[q], s0);
                    s1 = __hfma2(w[68 + q], b1p[q], s1);
                }
                uint4 ha2 = h0[18]; uint4 hb2 = h1[18];
                const __half2* a2 = (const __half2*)&ha2;
                const __half2* b2 = (const __half2*)&hb2;
                #pragma unroll
                for (int q = 0; q < 4; q++) {
                    s0 = __hfma2(w[72 + q], a2[q], s0);
                    s1 = __hfma2(w[72 + q], b2[q], s1);
                }
                float2 f0 = __half22float2(s0); acc0 += f0.x + f0.y;
                float2 f1 = __half22float2(s1); acc1 += f1.x + f1.y;
            }
            ghm[0][tid] = acc0 + bhv;
            ghm[1][tid] = acc1 + bhv;
        }
        __syncthreads();
        if (tid < 300) {
            const float* gh = ghm[nb];
            float r = __fdividef(1.f, 1.f + __expf(-(gir + gh[j])));
            float z = __fdividef(1.f, 1.f + __expf(-(giz + gh[HH + j])));
            float u = gin + r * gh[2 * HH + j];
            float e = __expf(-2.f * u);
            float n = __fdividef(2.f, 1.f + e) - 1.f;   // tanh(u), overflow-safe
            float h = hf[tid];
            float hn = (1.f - z) * n + z * h;
            hf[tid] = hn;
            hh[nb][j] = __float2half_rn(hn);
            *sqp = hn;
            gip += dstep;
            sqp += sstep;
        }
        __syncthreads();
    }
    if (tid < 300)
        g_hidden[(b0 + nb) * D2 + dir * HH + j] = hf[tid];
}

// ==========================================================================
// K3a0: ctxA[k][d] = battn[k][d] + attn_context[k,:] . Wattn[k][:300][d]
// ==========================================================================
__global__ void __launch_bounds__(320) ctxA_kernel(
    const float* __restrict__ attn_context, const float* __restrict__ Wattn,
    const float* __restrict__ battn)
{
    const int k = blockIdx.x;
    const int d = threadIdx.x;
    __shared__ float ac[D2];
    if (d < D2) ac[d] = attn_context[k * D2 + d];
    __syncthreads();
    if (d < D2) {
        float acc = battn[k * D2 + d];
        const float* wp = Wattn + (size_t)k * 600 * D2 + d;
        #pragma unroll 1
        for (int c = 0; c < D2; c += 4) {
            float w0 = wp[(size_t)(c + 0) * D2];
            float w1 = wp[(size_t)(c + 1) * D2];
            float w2 = wp[(size_t)(c + 2) * D2];
            float w3 = wp[(size_t)(c + 3) * D2];
            acc += ac[c] * w0 + ac[c + 1] * w1 + ac[c + 2] * w2 + ac[c + 3] * w3;
        }
        g_ctxA[k * D2 + d] = acc;
    }
}

// ==========================================================================
// K3a: context[b][k][d] = tanh(ctxA[k][d] + hidden[b,:] . Wattn[k][300:][d])
// ==========================================================================
__global__ void __launch_bounds__(320) context_kernel(const float* __restrict__ Wattn)
{
    const int k  = blockIdx.x;
    const int b0 = blockIdx.y * 4;
    const int d  = threadIdx.x;
    __shared__ float hid[4 * D2];
    for (int i = threadIdx.x; i < 4 * D2; i += blockDim.x) hid[i] = g_hidden[b0 * D2 + i];
    __syncthreads();
    if (d < D2) {
        float acc[4];
        const float base = g_ctxA[k * D2 + d];
        #pragma unroll
        for (int bb = 0; bb < 4; bb++) acc[bb] = base;
        const float* wp = Wattn + ((size_t)k * 600 + D2) * D2 + d;
        #pragma unroll 1
        for (int jj = 0; jj < D2; jj += 4) {
            float w0 = wp[(size_t)(jj + 0) * D2];
            float w1 = wp[(size_t)(jj + 1) * D2];
            float w2 = wp[(size_t)(jj + 2) * D2];
            float w3 = wp[(size_t)(jj + 3) * D2];
            #pragma unroll
            for (int bb = 0; bb < 4; bb++) {
                acc[bb] += hid[bb * D2 + jj] * w0 + hid[bb * D2 + jj + 1] * w1
                         + hid[bb * D2 + jj + 2] * w2 + hid[bb * D2 + jj + 3] * w3;
            }
        }
        #pragma unroll
        for (int bb = 0; bb < 4; bb++)
            g_context[((size_t)(b0 + bb) * KK + k) * D2 + d] = tanhf(acc[bb]);
    }
}

// ==========================================================================
// K3b: energy[b][t][k] = seq[b,t,:] . context[b,k,:]   — grid (B, 2 T-halves)
// ==========================================================================
__global__ void __launch_bounds__(256) energy_kernel()
{
    const int b  = blockIdx.x;
    const int th = blockIdx.y;          // T half
    __shared__ float ctx[KK * 301];
    __shared__ float seq_s[32 * D2];
    const int tid = threadIdx.x;
    for (int i = tid; i < KK * D2; i += 256) {
        int k = i / D2, d = i % D2;
        ctx[k * 301 + d] = g_context[((size_t)b * KK + k) * D2 + d];
    }
    const int tt = tid >> 3, kk = tid & 7;
    const int tbeg = th * 256;
    for (int t0 = tbeg; t0 < tbeg + 256; t0 += 32) {
        __syncthreads();
        for (int i = tid; i < 32 * D2; i += 256)
            seq_s[i] = g_seq[((size_t)b * TT + t0) * D2 + i];
        __syncthreads();
        if (kk < KK) {
            const float* sr = seq_s + tt * D2;
            const float* cr = ctx + kk * 301;
            float e = 0.f;
            #pragma unroll 4
            for (int d = 0; d < D2; d++) e += sr[d] * cr[d];
            g_energy[((size_t)b * TT + t0 + tt) * KK + kk] = e;
        }
    }
}

// ==========================================================================
// K3c: softmax over T per (b,k), in place on g_energy
// ==========================================================================
__global__ void __launch_bounds__(192) softmax_t()
{
    const int b = blockIdx.x;
    const int k = threadIdx.x >> 5;
    const int lane = threadIdx.x & 31;
    float v[16];
    float m = -1e30f;
    #pragma unroll
    for (int i = 0; i < 16; i++) {
        v[i] = g_energy[((size_t)b * TT + lane + i * 32) * KK + k];
        m = fmaxf(m, v[i]);
    }
    #pragma unroll
    for (int o = 16; o; o >>= 1) m = fmaxf(m, __shfl_xor_sync(0xffffffffu, m, o));
    float ssum = 0.f;
    #pragma unroll
    for (int i = 0; i < 16; i++) { v[i] = __expf(v[i] - m); ssum += v[i]; }
    #pragma unroll
    for (int o = 16; o; o >>= 1) ssum += __shfl_xor_sync(0xffffffffu, ssum, o);
    const float inv = 1.f / ssum;
    #pragma unroll
    for (int i = 0; i < 16; i++)
        g_energy[((size_t)b * TT + lane + i * 32) * KK + k] = v[i] * inv;
}

// ==========================================================================
// K3d: pooled partial[b][k][d] over T half  — grid (B, 2)
// ==========================================================================
__global__ void __launch_bounds__(320) pooled_kernel()
{
    const int b  = blockIdx.x;
    const int th = blockIdx.y;
    const int tid = threadIdx.x;
    __shared__ float seq_s[32 * D2];
    __shared__ float pr[32 * 8];
    float acc[KK];
    #pragma unroll
    for (int k = 0; k < KK; k++) acc[k] = 0.f;
    const int tbeg = th * 256;
    for (int t0 = tbeg; t0 < tbeg + 256; t0 += 32) {
        __syncthreads();
        for (int i = tid; i < 32 * D2; i += 320)
            seq_s[i] = g_seq[((size_t)b * TT + t0) * D2 + i];
        for (int i = tid; i < 32 * KK; i += 320) {
            int tt = i / KK, k = i % KK;
            pr[tt * 8 + k] = g_energy[((size_t)b * TT + t0 + tt) * KK + k];
        }
        __syncthreads();
        if (tid < D2) {
            #pragma unroll 4
            for (int tt = 0; tt < 32; tt++) {
                const float sv = seq_s[tt * D2 + tid];
                #pragma unroll
                for (int k = 0; k < KK; k++) acc[k] += sv * pr[tt * 8 + k];
            }
        }
    }
    if (tid < D2) {
        #pragma unroll
        for (int k = 0; k < KK; k++)
            g_pooled2[th][((size_t)b * KK + k) * D2 + tid] = acc[k];
    }
}

// ==========================================================================
// K3e: topic heads + logits + softmax + per-batch reg term
// ==========================================================================
__global__ void __launch_bounds__(128) head_kernel(
    const float* __restrict__ Wtop, const float* __restrict__ btop,
    const float* __restrict__ Wout, const float* __restrict__ bout,
    float* __restrict__ out)
{
    const int b = blockIdx.x;
    const int tid = threadIdx.x;
    __shared__ float pl[KK * D2];
    __shared__ float cx[KK * D2];
    __shared__ float tp[KK * THD];
    __shared__ float lg[CLSN];
    __shared__ float inorm[KK];
    __shared__ float gsq[KK * KK];
    for (int i = tid; i < KK * D2; i += 128) {
        pl[i] = g_pooled2[0][(size_t)b * KK * D2 + i]
              + g_pooled2[1][(size_t)b * KK * D2 + i];
        cx[i] = g_context[(size_t)b * KK * D2 + i];
    }
    __syncthreads();
    if (tid < KK * THD) {
        const int k = tid / THD, h = tid % THD;
        float a = btop[tid];
        const float* pk = pl + k * D2;
        for (int d = 0; d < D2; d++)
            a += pk[d] * Wtop[((size_t)k * D2 + d) * THD + h];
        tp[tid] = fmaxf(a, 0.f);
    }
    if (tid >= 120 && tid < 120 + KK) {
        const int k = tid - 120;
        const float* ck = cx + k * D2;
        float s = 0.f;
        for (int d = 0; d < D2; d++) s += ck[d] * ck[d];
        inorm[k] = 1.f / fmaxf(sqrtf(s), 1e-12f);
    }
    __syncthreads();
    if (tid < CLSN) {
        float L = bout[tid];
        for (int i = 0; i < KK * THD; i++) L += tp[i] * Wout[i * CLSN + tid];
        lg[tid] = L;
    }
    if (tid >= 32 && tid < 32 + KK * KK) {
        const int q = tid - 32;
        const int k = q / KK, j = q % KK;
        const float* ck = cx + k * D2;
        const float* cj = cx + j * D2;
        float gdot = 0.f;
        for (int d = 0; d < D2; d++) gdot += ck[d] * cj[d];
        gdot *= inorm[k] * inorm[j];
        const float diff = gdot - (k == j ? 1.f : 0.f);
        gsq[q] = diff * diff;
    }
    __syncthreads();
    if (tid < CLSN) {
        float m = lg[0];
        #pragma unroll
        for (int i = 1; i < CLSN; i++) m = fmaxf(m, lg[i]);
        float ss = 0.f;
        #pragma unroll
        for (int i = 0; i < CLSN; i++) ss += __expf(lg[i] - m);
        out[b * CLSN + tid] = __expf(lg[tid] - m) / ss;
    }
    if (tid == 0) {
        float ssum = 0.f;
        #pragma unroll
        for (int i = 0; i < KK * KK; i++) ssum += gsq[i];
        g_regb[b] = sqrtf(ssum);
    }
}

// ==========================================================================
// K3f: reg = mean_b(g_regb)
// ==========================================================================
__global__ void __launch_bounds__(128) reg_reduce(float* __restrict__ out, int out_size)
{
    __shared__ float sh[128];
    const int tid = threadIdx.x;
    sh[tid] = g_regb[tid];
    __syncthreads();
    for (int o = 64; o; o >>= 1) {
        if (tid < o) sh[tid] += sh[tid + o];
        __syncthreads();
    }
    if (tid == 0) out[out_size - 1] = sh[0] * (1.f / 128.f);
}

// ==========================================================================
extern "C" void kernel_launch(void* const* d_in, const int* in_sizes, int n_in,
                              void* d_out, int out_size)
{
    const float* x            = (const float*)d_in[0];
    const float* Wih_f        = (const float*)d_in[1];
    const float* Whh_f        = (const float*)d_in[2];
    const float* bih_f        = (const float*)d_in[3];
    const float* bhh_f        = (const float*)d_in[4];
    const float* Wih_b        = (const float*)d_in[5];
    const float* Whh_b        = (const float*)d_in[6];
    const float* bih_b        = (const float*)d_in[7];
    const float* bhh_b        = (const float*)d_in[8];
    const float* attn_context = (const float*)d_in[9];
    const float* Wattn        = (const float*)d_in[10];
    const float* battn        = (const float*)d_in[11];
    const float* Wtop         = (const float*)d_in[12];
    const float* btop         = (const float*)d_in[13];
    const float* Wout         = (const float*)d_in[14];
    const float* bout         = (const float*)d_in[15];
    float* out = (float*)d_out;

    cudaFuncSetAttribute(gi_gemm_mma, cudaFuncAttributeMaxDynamicSharedMemorySize, GI_SMEM);

    const size_t xtot = (size_t)BB * TT * KP;
    cvt_x<<<(unsigned)((xtot + 255) / 256), 256>>>(x);
    cvt_w<<<(NPAD * KP + 255) / 256, 256>>>(Wih_f, Wih_b);
    gi_gemm_mma<<<(BB * TT) / GBM, 256, GI_SMEM>>>(bih_f, bih_b);
    gru_scan<<<128, 480>>>(Whh_f, Whh_b, bhh_f, bhh_b);
    ctxA_kernel<<<KK, 320>>>(attn_context, Wattn, battn);
    context_kernel<<<dim3(KK, 32), 320>>>(Wattn);
    energy_kernel<<<dim3(BB, 2), 256>>>();
    softmax_t<<<BB, 192>>>();
    pooled_kernel<<<dim3(BB, 2), 320>>>();
    head_kernel<<<BB, 128>>>(Wtop, btop, Wout, bout, out);
    reg_reduce<<<1, 128>>>(out, out_size);
}